// round 1
// baseline (speedup 1.0000x reference)
#include <cuda_runtime.h>

#define B_ 4
#define N_ 2048
#define C_ 1024
#define H_ 16
#define D_ 64
#define M_ (B_*N_)

// Scratch (device globals — no runtime allocation allowed)
__device__ float g_q[(size_t)B_*H_*N_*D_];
__device__ float g_k[(size_t)B_*H_*N_*D_];
__device__ float g_v[(size_t)B_*H_*N_*D_];
__device__ float g_att[(size_t)B_*N_*C_];

// ---------------------------------------------------------------------------
// GEMM 1: qkv = x @ qkv_w^T, scattered into Q/K/V [B,H,N,D]
// 128x128 tile, K-step 8, 8x8 per thread, 256 threads
// ---------------------------------------------------------------------------
__global__ __launch_bounds__(256) void qkv_gemm(const float* __restrict__ A,
                                                const float* __restrict__ W)
{
    __shared__ float As[8][128];
    __shared__ float Bs[8][128];
    int tid = threadIdx.x;
    int bm = blockIdx.y * 128;
    int bn = blockIdx.x * 128;
    int lr = tid >> 1;
    int lc = (tid & 1) << 2;
    int mB = (tid >> 4) << 3;
    int nB = (tid & 15) << 3;

    float acc[8][8];
    #pragma unroll
    for (int i = 0; i < 8; i++)
        #pragma unroll
        for (int j = 0; j < 8; j++) acc[i][j] = 0.f;

    const float* Aptr = A + (size_t)(bm + lr) * C_ + lc;
    const float* Wptr = W + (size_t)(bn + lr) * C_ + lc;

    for (int k0 = 0; k0 < C_; k0 += 8) {
        float4 av = *(const float4*)(Aptr + k0);
        float4 bv = *(const float4*)(Wptr + k0);
        As[lc + 0][lr] = av.x; As[lc + 1][lr] = av.y;
        As[lc + 2][lr] = av.z; As[lc + 3][lr] = av.w;
        Bs[lc + 0][lr] = bv.x; Bs[lc + 1][lr] = bv.y;
        Bs[lc + 2][lr] = bv.z; Bs[lc + 3][lr] = bv.w;
        __syncthreads();
        #pragma unroll
        for (int kk = 0; kk < 8; kk++) {
            float4 a0 = *(const float4*)&As[kk][mB];
            float4 a1 = *(const float4*)&As[kk][mB + 4];
            float4 b0 = *(const float4*)&Bs[kk][nB];
            float4 b1 = *(const float4*)&Bs[kk][nB + 4];
            float a[8] = {a0.x, a0.y, a0.z, a0.w, a1.x, a1.y, a1.z, a1.w};
            float b[8] = {b0.x, b0.y, b0.z, b0.w, b1.x, b1.y, b1.z, b1.w};
            #pragma unroll
            for (int i = 0; i < 8; i++)
                #pragma unroll
                for (int j = 0; j < 8; j++)
                    acc[i][j] = fmaf(a[i], b[j], acc[i][j]);
        }
        __syncthreads();
    }

    // Scatter: o -> (three, h, d); row m -> (b, n)
    #pragma unroll
    for (int i = 0; i < 8; i++) {
        int m = bm + mB + i;
        int b = m >> 11;          // /2048
        int n = m & (N_ - 1);
        #pragma unroll
        for (int j = 0; j < 8; j++) {
            int o = bn + nB + j;
            int three = o >> 10;
            int rem = o & 1023;
            int h = rem >> 6;
            int d = rem & 63;
            float* dst = (three == 0) ? g_q : (three == 1 ? g_k : g_v);
            dst[(((size_t)b * H_ + h) * N_ + n) * D_ + d] = acc[i][j];
        }
    }
}

// ---------------------------------------------------------------------------
// GEMM 2: out = g_att @ proj_w^T + proj_b
// ---------------------------------------------------------------------------
__global__ __launch_bounds__(256) void proj_gemm(const float* __restrict__ W,
                                                 const float* __restrict__ bias,
                                                 float* __restrict__ out)
{
    __shared__ float As[8][128];
    __shared__ float Bs[8][128];
    int tid = threadIdx.x;
    int bm = blockIdx.y * 128;
    int bn = blockIdx.x * 128;
    int lr = tid >> 1;
    int lc = (tid & 1) << 2;
    int mB = (tid >> 4) << 3;
    int nB = (tid & 15) << 3;

    float acc[8][8];
    #pragma unroll
    for (int i = 0; i < 8; i++)
        #pragma unroll
        for (int j = 0; j < 8; j++) acc[i][j] = 0.f;

    const float* Aptr = g_att + (size_t)(bm + lr) * C_ + lc;
    const float* Wptr = W + (size_t)(bn + lr) * C_ + lc;

    for (int k0 = 0; k0 < C_; k0 += 8) {
        float4 av = *(const float4*)(Aptr + k0);
        float4 bv = *(const float4*)(Wptr + k0);
        As[lc + 0][lr] = av.x; As[lc + 1][lr] = av.y;
        As[lc + 2][lr] = av.z; As[lc + 3][lr] = av.w;
        Bs[lc + 0][lr] = bv.x; Bs[lc + 1][lr] = bv.y;
        Bs[lc + 2][lr] = bv.z; Bs[lc + 3][lr] = bv.w;
        __syncthreads();
        #pragma unroll
        for (int kk = 0; kk < 8; kk++) {
            float4 a0 = *(const float4*)&As[kk][mB];
            float4 a1 = *(const float4*)&As[kk][mB + 4];
            float4 b0 = *(const float4*)&Bs[kk][nB];
            float4 b1 = *(const float4*)&Bs[kk][nB + 4];
            float a[8] = {a0.x, a0.y, a0.z, a0.w, a1.x, a1.y, a1.z, a1.w};
            float b[8] = {b0.x, b0.y, b0.z, b0.w, b1.x, b1.y, b1.z, b1.w};
            #pragma unroll
            for (int i = 0; i < 8; i++)
                #pragma unroll
                for (int j = 0; j < 8; j++)
                    acc[i][j] = fmaf(a[i], b[j], acc[i][j]);
        }
        __syncthreads();
    }

    #pragma unroll
    for (int i = 0; i < 8; i++) {
        int m = bm + mB + i;
        #pragma unroll
        for (int j = 0; j < 8; j++) {
            int o = bn + nB + j;
            out[(size_t)m * C_ + o] = acc[i][j] + bias[o];
        }
    }
}

// ---------------------------------------------------------------------------
// Causal flash attention: block per (qtile=64 rows, head, batch), 256 threads.
// Online softmax in smem, O accumulator (4x4 per thread) in registers.
// ---------------------------------------------------------------------------
#define P_ 65   // smem pitch (floats)

__global__ __launch_bounds__(256) void attn_kernel()
{
    extern __shared__ float sm[];
    float* Qs = sm;                 // [d][row], 64*P_  (transposed)
    float* Ks = Qs + 64 * P_;       // [d][key], transposed
    float* Vs = Ks + 64 * P_;       // [key][d]
    float* Ss = Vs + 64 * P_;       // [row][col]
    float* m_s  = Ss + 64 * P_;     // 64
    float* l_s  = m_s + 64;         // 64
    float* al_s = l_s + 64;         // 64

    int qt = blockIdx.x, h = blockIdx.y, b = blockIdx.z;
    int tid = threadIdx.x;
    int r0 = (tid >> 4) * 4;        // 4 rows owned
    int c0 = (tid & 15) * 4;        // 4 cols (S) / 4 dims (O) owned
    const float scale = 0.125f;     // D^-0.5

    const float* Qg = g_q + ((size_t)b * H_ + h) * N_ * D_;
    const float* Kg = g_k + ((size_t)b * H_ + h) * N_ * D_;
    const float* Vg = g_v + ((size_t)b * H_ + h) * N_ * D_;

    // Load Q tile transposed: Qs[d][r]
    {
        int row = tid >> 4;
        int d4  = (tid & 15) * 4;
        #pragma unroll
        for (int p = 0; p < 4; p++) {
            int r = row + p * 16;
            float4 v = *(const float4*)(Qg + (size_t)(qt * 64 + r) * D_ + d4);
            Qs[(d4 + 0) * P_ + r] = v.x;
            Qs[(d4 + 1) * P_ + r] = v.y;
            Qs[(d4 + 2) * P_ + r] = v.z;
            Qs[(d4 + 3) * P_ + r] = v.w;
        }
    }
    if (tid < 64) { m_s[tid] = -1e30f; l_s[tid] = 0.f; }

    float O[4][4];
    #pragma unroll
    for (int i = 0; i < 4; i++)
        #pragma unroll
        for (int j = 0; j < 4; j++) O[i][j] = 0.f;

    for (int kt = 0; kt <= qt; kt++) {
        __syncthreads();   // prior iteration's reads of Ks/Vs/Ss complete
        // Load K (transposed) + V tiles
        {
            int row = tid >> 4;
            int d4  = (tid & 15) * 4;
            #pragma unroll
            for (int p = 0; p < 4; p++) {
                int r = row + p * 16;
                float4 kv = *(const float4*)(Kg + (size_t)(kt * 64 + r) * D_ + d4);
                Ks[(d4 + 0) * P_ + r] = kv.x;
                Ks[(d4 + 1) * P_ + r] = kv.y;
                Ks[(d4 + 2) * P_ + r] = kv.z;
                Ks[(d4 + 3) * P_ + r] = kv.w;
                float4 vv = *(const float4*)(Vg + (size_t)(kt * 64 + r) * D_ + d4);
                Vs[r * P_ + d4 + 0] = vv.x;
                Vs[r * P_ + d4 + 1] = vv.y;
                Vs[r * P_ + d4 + 2] = vv.z;
                Vs[r * P_ + d4 + 3] = vv.w;
            }
        }
        __syncthreads();

        // S = Q K^T (4x4 per thread)
        float s[4][4];
        #pragma unroll
        for (int i = 0; i < 4; i++)
            #pragma unroll
            for (int j = 0; j < 4; j++) s[i][j] = 0.f;

        #pragma unroll 8
        for (int d = 0; d < 64; d++) {
            float qv[4], kv[4];
            #pragma unroll
            for (int i = 0; i < 4; i++) qv[i] = Qs[d * P_ + r0 + i];
            #pragma unroll
            for (int j = 0; j < 4; j++) kv[j] = Ks[d * P_ + c0 + j];
            #pragma unroll
            for (int i = 0; i < 4; i++)
                #pragma unroll
                for (int j = 0; j < 4; j++)
                    s[i][j] = fmaf(qv[i], kv[j], s[i][j]);
        }

        bool diag = (kt == qt);
        #pragma unroll
        for (int i = 0; i < 4; i++)
            #pragma unroll
            for (int j = 0; j < 4; j++) {
                float v = s[i][j] * scale;
                if (diag && (c0 + j > r0 + i)) v = -1e30f;
                Ss[(r0 + i) * P_ + c0 + j] = v;
            }
        __syncthreads();

        // Per-row online softmax (64 row-owner threads)
        if (tid < 64) {
            int r = tid;
            float* row = Ss + r * P_;
            float mOld = m_s[r];
            float mNew = mOld;
            #pragma unroll 8
            for (int c = 0; c < 64; c++) mNew = fmaxf(mNew, row[c]);
            float alpha = __expf(mOld - mNew);
            float lsum = 0.f;
            #pragma unroll 8
            for (int c = 0; c < 64; c++) {
                float p = __expf(row[c] - mNew);
                row[c] = p;
                lsum += p;
            }
            m_s[r]  = mNew;
            l_s[r]  = l_s[r] * alpha + lsum;
            al_s[r] = alpha;
        }
        __syncthreads();

        // O = O*alpha + P @ V
        #pragma unroll
        for (int i = 0; i < 4; i++) {
            float a = al_s[r0 + i];
            #pragma unroll
            for (int j = 0; j < 4; j++) O[i][j] *= a;
        }
        #pragma unroll 4
        for (int c = 0; c < 64; c++) {
            float pv[4], vv[4];
            #pragma unroll
            for (int i = 0; i < 4; i++) pv[i] = Ss[(r0 + i) * P_ + c];
            #pragma unroll
            for (int j = 0; j < 4; j++) vv[j] = Vs[c * P_ + c0 + j];
            #pragma unroll
            for (int i = 0; i < 4; i++)
                #pragma unroll
                for (int j = 0; j < 4; j++)
                    O[i][j] = fmaf(pv[i], vv[j], O[i][j]);
        }
    }

    // Normalize + write [B,N,C]
    #pragma unroll
    for (int i = 0; i < 4; i++) {
        float inv = 1.f / l_s[r0 + i];
        int q = qt * 64 + r0 + i;
        #pragma unroll
        for (int j = 0; j < 4; j++)
            g_att[((size_t)b * N_ + q) * C_ + h * 64 + c0 + j] = O[i][j] * inv;
    }
}

// ---------------------------------------------------------------------------
extern "C" void kernel_launch(void* const* d_in, const int* in_sizes, int n_in,
                              void* d_out, int out_size)
{
    const float* x      = (const float*)d_in[0];
    const float* qkv_w  = (const float*)d_in[1];
    const float* proj_w = (const float*)d_in[2];
    const float* proj_b = (const float*)d_in[3];
    float* out = (float*)d_out;

    qkv_gemm<<<dim3(24, 64), 256>>>(x, qkv_w);

    int smem = (4 * 64 * P_ + 3 * 64) * (int)sizeof(float);
    cudaFuncSetAttribute(attn_kernel, cudaFuncAttributeMaxDynamicSharedMemorySize, smem);
    attn_kernel<<<dim3(N_ / 64, H_, B_), 256, smem>>>();

    proj_gemm<<<dim3(8, 64), 256>>>(proj_w, proj_b, out);
}

// round 2
// speedup vs baseline: 3.4224x; 3.4224x over previous
#include <cuda_runtime.h>

#define B_ 4
#define N_ 2048
#define C_ 1024
#define H_ 16
#define D_ 64

// Scratch (device globals — no runtime allocation allowed)
__device__ float g_q[(size_t)B_*H_*N_*D_];
__device__ float g_k[(size_t)B_*H_*N_*D_];
__device__ float g_v[(size_t)B_*H_*N_*D_];
__device__ float g_att[(size_t)B_*N_*C_];

__device__ __forceinline__ unsigned f2tf(float x) {
    unsigned u; asm("cvt.rna.tf32.f32 %0, %1;" : "=r"(u) : "f"(x)); return u;
}
__device__ __forceinline__ void mma8(float* c, const unsigned* a, const unsigned* b) {
    asm volatile("mma.sync.aligned.m16n8k8.row.col.f32.tf32.tf32.f32 "
        "{%0,%1,%2,%3}, {%4,%5,%6,%7}, {%8,%9}, {%0,%1,%2,%3};"
        : "+f"(c[0]), "+f"(c[1]), "+f"(c[2]), "+f"(c[3])
        : "r"(a[0]), "r"(a[1]), "r"(a[2]), "r"(a[3]), "r"(b[0]), "r"(b[1]));
}
__device__ __forceinline__ void cpasync16(unsigned saddr, const void* g) {
    asm volatile("cp.async.cg.shared.global [%0], [%1], 16;" :: "r"(saddr), "l"(g));
}

// ---------------------------------------------------------------------------
// Shared GEMM core: C_tile[128x128] = A[128xK] * W[128xK]^T, K=1024, tf32 MMA.
// Smem [m][k] pitch 36 (conflict-free for m16n8k8 tf32 fragment pattern).
// cp.async double-buffered, KC=32.
// ---------------------------------------------------------------------------
#define GP 36
#define GTILE (128*GP)
#define GSTAGE (2*GTILE)

__device__ __forceinline__ void gemm128(const float* __restrict__ A,
                                        const float* __restrict__ W,
                                        int bm, int bn,
                                        float acc[4][4][4], float* sm)
{
    int tid = threadIdx.x;
    int wid = tid >> 5, lane = tid & 31;
    int wm = wid >> 2, wn = wid & 3;          // 2 x 4 warp grid
    int g = lane >> 2, tg = lane & 3;

    int lm = tid >> 3;                        // loader row (0..31), +32*t
    int lc4 = (tid & 7) * 4;                  // loader k offset (floats)

    unsigned sbase = (unsigned)__cvta_generic_to_shared(sm);

    const int NS = C_ / 32;

    // prologue: stage 0 -> buffer 0
    #pragma unroll
    for (int t = 0; t < 4; t++) {
        int m = lm + t * 32;
        cpasync16(sbase + (unsigned)(m * GP + lc4) * 4u,
                  A + (size_t)(bm + m) * C_ + lc4);
        cpasync16(sbase + (unsigned)(GTILE + m * GP + lc4) * 4u,
                  W + (size_t)(bn + m) * C_ + lc4);
    }
    asm volatile("cp.async.commit_group;" ::: "memory");

    int buf = 0;
    for (int s = 0; s < NS; s++) {
        if (s + 1 < NS) {
            int nb = buf ^ 1;
            int kc = (s + 1) * 32;
            #pragma unroll
            for (int t = 0; t < 4; t++) {
                int m = lm + t * 32;
                cpasync16(sbase + (unsigned)(nb * GSTAGE + m * GP + lc4) * 4u,
                          A + (size_t)(bm + m) * C_ + kc + lc4);
                cpasync16(sbase + (unsigned)(nb * GSTAGE + GTILE + m * GP + lc4) * 4u,
                          W + (size_t)(bn + m) * C_ + kc + lc4);
            }
        }
        asm volatile("cp.async.commit_group;" ::: "memory");
        asm volatile("cp.async.wait_group 1;" ::: "memory");
        __syncthreads();

        const float* As = sm + buf * GSTAGE;
        const float* Bs = As + GTILE;
        #pragma unroll
        for (int ks = 0; ks < 4; ks++) {
            int k0 = ks * 8;
            unsigned af[4][4], bf[4][2];
            #pragma unroll
            for (int i = 0; i < 4; i++) {
                int r = wm * 64 + i * 16 + g;
                af[i][0] = f2tf(As[r * GP + k0 + tg]);
                af[i][1] = f2tf(As[(r + 8) * GP + k0 + tg]);
                af[i][2] = f2tf(As[r * GP + k0 + tg + 4]);
                af[i][3] = f2tf(As[(r + 8) * GP + k0 + tg + 4]);
            }
            #pragma unroll
            for (int j = 0; j < 4; j++) {
                int n = wn * 32 + j * 8 + g;
                bf[j][0] = f2tf(Bs[n * GP + k0 + tg]);
                bf[j][1] = f2tf(Bs[n * GP + k0 + tg + 4]);
            }
            #pragma unroll
            for (int i = 0; i < 4; i++)
                #pragma unroll
                for (int j = 0; j < 4; j++)
                    mma8(acc[i][j], af[i], bf[j]);
        }
        __syncthreads();
        buf ^= 1;
    }
}

// ---------------------------------------------------------------------------
// GEMM 1: qkv = x @ qkv_w^T, scattered into Q/K/V [B,H,N,D]
// ---------------------------------------------------------------------------
__global__ __launch_bounds__(256) void qkv_gemm(const float* __restrict__ A,
                                                const float* __restrict__ W)
{
    extern __shared__ float sm[];
    int bm = blockIdx.y * 128, bn = blockIdx.x * 128;
    float acc[4][4][4];
    #pragma unroll
    for (int i = 0; i < 4; i++)
        #pragma unroll
        for (int j = 0; j < 4; j++)
            #pragma unroll
            for (int q = 0; q < 4; q++) acc[i][j][q] = 0.f;

    gemm128(A, W, bm, bn, acc, sm);

    int tid = threadIdx.x, wid = tid >> 5, lane = tid & 31;
    int wm = wid >> 2, wn = wid & 3;
    int g = lane >> 2, tg = lane & 3;

    #pragma unroll
    for (int i = 0; i < 4; i++) {
        #pragma unroll
        for (int j = 0; j < 4; j++) {
            int col = bn + wn * 32 + j * 8 + 2 * tg;
            int three = col >> 10, rem = col & 1023;
            int h = rem >> 6, d = rem & 63;
            float* dst = (three == 0) ? g_q : (three == 1 ? g_k : g_v);
            #pragma unroll
            for (int half = 0; half < 2; half++) {
                int row = bm + wm * 64 + i * 16 + g + half * 8;
                int b = row >> 11, n = row & (N_ - 1);
                float2 v = {acc[i][j][half * 2], acc[i][j][half * 2 + 1]};
                *(float2*)(dst + (((size_t)b * H_ + h) * N_ + n) * D_ + d) = v;
            }
        }
    }
}

// ---------------------------------------------------------------------------
// GEMM 2: out = g_att @ proj_w^T + proj_b
// ---------------------------------------------------------------------------
__global__ __launch_bounds__(256) void proj_gemm(const float* __restrict__ W,
                                                 const float* __restrict__ bias,
                                                 float* __restrict__ out)
{
    extern __shared__ float sm[];
    int bm = blockIdx.y * 128, bn = blockIdx.x * 128;
    float acc[4][4][4];
    #pragma unroll
    for (int i = 0; i < 4; i++)
        #pragma unroll
        for (int j = 0; j < 4; j++)
            #pragma unroll
            for (int q = 0; q < 4; q++) acc[i][j][q] = 0.f;

    gemm128(g_att, W, bm, bn, acc, sm);

    int tid = threadIdx.x, wid = tid >> 5, lane = tid & 31;
    int wm = wid >> 2, wn = wid & 3;
    int g = lane >> 2, tg = lane & 3;

    #pragma unroll
    for (int i = 0; i < 4; i++) {
        #pragma unroll
        for (int j = 0; j < 4; j++) {
            int col = bn + wn * 32 + j * 8 + 2 * tg;
            float b0 = bias[col], b1 = bias[col + 1];
            #pragma unroll
            for (int half = 0; half < 2; half++) {
                int row = bm + wm * 64 + i * 16 + g + half * 8;
                float2 v = {acc[i][j][half * 2] + b0, acc[i][j][half * 2 + 1] + b1};
                *(float2*)(out + (size_t)row * C_ + col) = v;
            }
        }
    }
}

// ---------------------------------------------------------------------------
// Causal flash attention, tf32 MMA. Block = (qtile 64 rows, head, batch),
// 4 warps, each warp owns 16 q-rows. S and PV via m16n8k8 tf32.
// ---------------------------------------------------------------------------
#define AP 68

__global__ __launch_bounds__(128) void attn_kernel()
{
    extern __shared__ float sm[];
    float* Qs = sm;              // [64][AP] tf32 bits
    float* Ks = Qs + 64 * AP;    // [key][d]
    float* Vs = Ks + 64 * AP;    // [key][d]
    float* Ss = Vs + 64 * AP;    // [q][key] P tf32 bits

    int qt = blockIdx.x, h = blockIdx.y, b = blockIdx.z;
    int tid = threadIdx.x, w = tid >> 5, lane = tid & 31;
    int g = lane >> 2, tg = lane & 3;

    const float* Qg = g_q + ((size_t)b * H_ + h) * N_ * D_;
    const float* Kg = g_k + ((size_t)b * H_ + h) * N_ * D_;
    const float* Vg = g_v + ((size_t)b * H_ + h) * N_ * D_;

    // Load Q tile (tf32-rounded)
    #pragma unroll
    for (int t = 0; t < 8; t++) {
        int idx = tid + t * 128;
        int r = idx >> 4, c4 = (idx & 15) * 4;
        float4 v = *(const float4*)(Qg + (size_t)(qt * 64 + r) * D_ + c4);
        float* d = Qs + r * AP + c4;
        d[0] = __uint_as_float(f2tf(v.x));
        d[1] = __uint_as_float(f2tf(v.y));
        d[2] = __uint_as_float(f2tf(v.z));
        d[3] = __uint_as_float(f2tf(v.w));
    }

    float o[8][4];
    #pragma unroll
    for (int nt = 0; nt < 8; nt++)
        #pragma unroll
        for (int q = 0; q < 4; q++) o[nt][q] = 0.f;
    float m0 = -1e30f, m1 = -1e30f, l0 = 0.f, l1 = 0.f;

    int r = w * 16 + g;

    for (int kt = 0; kt <= qt; kt++) {
        __syncthreads();
        // Load K, V tiles (tf32-rounded)
        #pragma unroll
        for (int t = 0; t < 8; t++) {
            int idx = tid + t * 128;
            int rr = idx >> 4, c4 = (idx & 15) * 4;
            float4 kv = *(const float4*)(Kg + (size_t)(kt * 64 + rr) * D_ + c4);
            float* dk = Ks + rr * AP + c4;
            dk[0] = __uint_as_float(f2tf(kv.x));
            dk[1] = __uint_as_float(f2tf(kv.y));
            dk[2] = __uint_as_float(f2tf(kv.z));
            dk[3] = __uint_as_float(f2tf(kv.w));
            float4 vv = *(const float4*)(Vg + (size_t)(kt * 64 + rr) * D_ + c4);
            float* dv = Vs + rr * AP + c4;
            dv[0] = __uint_as_float(f2tf(vv.x));
            dv[1] = __uint_as_float(f2tf(vv.y));
            dv[2] = __uint_as_float(f2tf(vv.z));
            dv[3] = __uint_as_float(f2tf(vv.w));
        }
        __syncthreads();

        // S = Q K^T
        float s[8][4];
        #pragma unroll
        for (int nt = 0; nt < 8; nt++)
            #pragma unroll
            for (int q = 0; q < 4; q++) s[nt][q] = 0.f;

        #pragma unroll
        for (int ks = 0; ks < 8; ks++) {
            int k0 = ks * 8;
            unsigned qa[4];
            qa[0] = __float_as_uint(Qs[r * AP + k0 + tg]);
            qa[1] = __float_as_uint(Qs[(r + 8) * AP + k0 + tg]);
            qa[2] = __float_as_uint(Qs[r * AP + k0 + tg + 4]);
            qa[3] = __float_as_uint(Qs[(r + 8) * AP + k0 + tg + 4]);
            #pragma unroll
            for (int nt = 0; nt < 8; nt++) {
                unsigned kb[2];
                int n = nt * 8 + g;
                kb[0] = __float_as_uint(Ks[n * AP + k0 + tg]);
                kb[1] = __float_as_uint(Ks[n * AP + k0 + tg + 4]);
                mma8(s[nt], qa, kb);
            }
        }

        // scale + causal mask (diagonal tile only)
        const float sc = 0.125f;
        #pragma unroll
        for (int nt = 0; nt < 8; nt++) {
            s[nt][0] *= sc; s[nt][1] *= sc; s[nt][2] *= sc; s[nt][3] *= sc;
        }
        if (kt == qt) {
            #pragma unroll
            for (int nt = 0; nt < 8; nt++) {
                int c0 = nt * 8 + 2 * tg;
                if (c0 > r)         s[nt][0] = -1e30f;
                if (c0 + 1 > r)     s[nt][1] = -1e30f;
                if (c0 > r + 8)     s[nt][2] = -1e30f;
                if (c0 + 1 > r + 8) s[nt][3] = -1e30f;
            }
        }

        // online softmax (rows r and r+8, shared with lanes tg 0..3)
        float mx0 = -1e30f, mx1 = -1e30f;
        #pragma unroll
        for (int nt = 0; nt < 8; nt++) {
            mx0 = fmaxf(mx0, fmaxf(s[nt][0], s[nt][1]));
            mx1 = fmaxf(mx1, fmaxf(s[nt][2], s[nt][3]));
        }
        mx0 = fmaxf(mx0, __shfl_xor_sync(0xffffffffu, mx0, 1));
        mx0 = fmaxf(mx0, __shfl_xor_sync(0xffffffffu, mx0, 2));
        mx1 = fmaxf(mx1, __shfl_xor_sync(0xffffffffu, mx1, 1));
        mx1 = fmaxf(mx1, __shfl_xor_sync(0xffffffffu, mx1, 2));

        float nm0 = fmaxf(m0, mx0), nm1 = fmaxf(m1, mx1);
        float a0 = __expf(m0 - nm0), a1 = __expf(m1 - nm1);
        m0 = nm0; m1 = nm1;

        float ls0 = 0.f, ls1 = 0.f;
        #pragma unroll
        for (int nt = 0; nt < 8; nt++) {
            float p0 = __expf(s[nt][0] - nm0);
            float p1 = __expf(s[nt][1] - nm0);
            float p2 = __expf(s[nt][2] - nm1);
            float p3 = __expf(s[nt][3] - nm1);
            ls0 += p0 + p1; ls1 += p2 + p3;
            int c0 = nt * 8 + 2 * tg;
            Ss[r * AP + c0]           = __uint_as_float(f2tf(p0));
            Ss[r * AP + c0 + 1]       = __uint_as_float(f2tf(p1));
            Ss[(r + 8) * AP + c0]     = __uint_as_float(f2tf(p2));
            Ss[(r + 8) * AP + c0 + 1] = __uint_as_float(f2tf(p3));
        }
        ls0 += __shfl_xor_sync(0xffffffffu, ls0, 1);
        ls0 += __shfl_xor_sync(0xffffffffu, ls0, 2);
        ls1 += __shfl_xor_sync(0xffffffffu, ls1, 1);
        ls1 += __shfl_xor_sync(0xffffffffu, ls1, 2);
        l0 = l0 * a0 + ls0;
        l1 = l1 * a1 + ls1;

        #pragma unroll
        for (int nt = 0; nt < 8; nt++) {
            o[nt][0] *= a0; o[nt][1] *= a0;
            o[nt][2] *= a1; o[nt][3] *= a1;
        }
        __syncwarp();

        // O += P V
        #pragma unroll
        for (int ks = 0; ks < 8; ks++) {
            int k0 = ks * 8;
            unsigned pa[4];
            pa[0] = __float_as_uint(Ss[r * AP + k0 + tg]);
            pa[1] = __float_as_uint(Ss[(r + 8) * AP + k0 + tg]);
            pa[2] = __float_as_uint(Ss[r * AP + k0 + tg + 4]);
            pa[3] = __float_as_uint(Ss[(r + 8) * AP + k0 + tg + 4]);
            #pragma unroll
            for (int nt = 0; nt < 8; nt++) {
                unsigned vb[2];
                int n = nt * 8 + g;
                vb[0] = __float_as_uint(Vs[(k0 + tg) * AP + n]);
                vb[1] = __float_as_uint(Vs[(k0 + tg + 4) * AP + n]);
                mma8(o[nt], pa, vb);
            }
        }
    }

    // epilogue: normalize + write [B,N,C]
    float i0 = 1.f / l0, i1 = 1.f / l1;
    int q0 = qt * 64 + r;
    float* Og = g_att + (size_t)b * N_ * C_ + (size_t)h * 64;
    #pragma unroll
    for (int nt = 0; nt < 8; nt++) {
        int d = nt * 8 + 2 * tg;
        float2 v0 = {o[nt][0] * i0, o[nt][1] * i0};
        *(float2*)(Og + (size_t)q0 * C_ + d) = v0;
        float2 v1 = {o[nt][2] * i1, o[nt][3] * i1};
        *(float2*)(Og + (size_t)(q0 + 8) * C_ + d) = v1;
    }
}

// ---------------------------------------------------------------------------
extern "C" void kernel_launch(void* const* d_in, const int* in_sizes, int n_in,
                              void* d_out, int out_size)
{
    const float* x      = (const float*)d_in[0];
    const float* qkv_w  = (const float*)d_in[1];
    const float* proj_w = (const float*)d_in[2];
    const float* proj_b = (const float*)d_in[3];
    float* out = (float*)d_out;

    int gsmem = 2 * GSTAGE * (int)sizeof(float);   // 73728 B
    cudaFuncSetAttribute(qkv_gemm, cudaFuncAttributeMaxDynamicSharedMemorySize, gsmem);
    cudaFuncSetAttribute(proj_gemm, cudaFuncAttributeMaxDynamicSharedMemorySize, gsmem);

    int asmem = 4 * 64 * AP * (int)sizeof(float);  // 69632 B
    cudaFuncSetAttribute(attn_kernel, cudaFuncAttributeMaxDynamicSharedMemorySize, asmem);

    qkv_gemm<<<dim3(24, 64), 256, gsmem>>>(x, qkv_w);
    attn_kernel<<<dim3(N_ / 64, H_, B_), 128, asmem>>>();
    proj_gemm<<<dim3(8, 64), 256, gsmem>>>(proj_w, proj_b, out);
}

// round 5
// speedup vs baseline: 4.1230x; 1.2047x over previous
#include <cuda_runtime.h>

#define B_ 4
#define N_ 2048
#define C_ 1024
#define H_ 16
#define D_ 64

// Scratch (device globals — no runtime allocation allowed)
__device__ float g_q[(size_t)B_*H_*N_*D_];
__device__ float g_k[(size_t)B_*H_*N_*D_];
__device__ float g_v[(size_t)B_*H_*N_*D_];
__device__ float g_att[(size_t)B_*N_*C_];

__device__ __forceinline__ unsigned f2tf(float x) {
    unsigned u; asm("cvt.rna.tf32.f32 %0, %1;" : "=r"(u) : "f"(x)); return u;
}
__device__ __forceinline__ void mma8(float* c, const unsigned* a, const unsigned* b) {
    asm volatile("mma.sync.aligned.m16n8k8.row.col.f32.tf32.tf32.f32 "
        "{%0,%1,%2,%3}, {%4,%5,%6,%7}, {%8,%9}, {%0,%1,%2,%3};"
        : "+f"(c[0]), "+f"(c[1]), "+f"(c[2]), "+f"(c[3])
        : "r"(a[0]), "r"(a[1]), "r"(a[2]), "r"(a[3]), "r"(b[0]), "r"(b[1]));
}
__device__ __forceinline__ void ldsm4(unsigned* r, unsigned addr) {
    asm volatile("ldmatrix.sync.aligned.m8n8.x4.shared.b16 {%0,%1,%2,%3}, [%4];"
        : "=r"(r[0]), "=r"(r[1]), "=r"(r[2]), "=r"(r[3]) : "r"(addr));
}

// ---------------------------------------------------------------------------
// GEMM core: C_tile[128x128] = A[128xK] * W[128xK]^T, K=1024, tf32 MMA.
// Smem pitch 32, XOR swizzle. cvt at store, ldmatrix frags, LDG->reg double
// buffer. 256 threads, 8 warps (2x4), warp tile 64x32.
// ---------------------------------------------------------------------------
#define KC 32
#define AW (128*KC)   // words per matrix per buffer

__device__ __forceinline__ unsigned gswz(int row, int col) {  // word idx, col%4==0
    return (unsigned)(row * KC + ((((col >> 2) ^ (row & 7)) << 2)));
}

__device__ __forceinline__ void gemm128(const float* __restrict__ A,
                                        const float* __restrict__ W,
                                        int bm, int bn,
                                        float acc[4][4][4], float* sm)
{
    int tid = threadIdx.x, wid = tid >> 5, lane = tid & 31;
    int wm = wid >> 2, wn = wid & 3;
    unsigned sbase = (unsigned)__cvta_generic_to_shared(sm);

    int lrow = tid >> 3;            // 0..31 (+32t)
    int lcol = (tid & 7) * 4;

    // per-lane ldmatrix row/col components
    int arow_l = (lane & 7) + (((lane >> 3) & 1) << 3);
    int acol_l = (lane >> 4) << 2;
    int brow_l = (lane & 7) + (((lane >> 4) & 1) << 3);
    int bcol_l = ((lane >> 3) & 1) << 2;

    float4 ra[4], rb[4];
    #pragma unroll
    for (int t = 0; t < 4; t++) {
        int r = lrow + t * 32;
        ra[t] = *(const float4*)(A + (size_t)(bm + r) * C_ + lcol);
        rb[t] = *(const float4*)(W + (size_t)(bn + r) * C_ + lcol);
    }
    // cvt + STS stage 0 -> buf 0
    #pragma unroll
    for (int t = 0; t < 4; t++) {
        int r = lrow + t * 32;
        unsigned w = gswz(r, lcol);
        uint4 ua = {f2tf(ra[t].x), f2tf(ra[t].y), f2tf(ra[t].z), f2tf(ra[t].w)};
        *(uint4*)(sm + w) = ua;
        uint4 ub = {f2tf(rb[t].x), f2tf(rb[t].y), f2tf(rb[t].z), f2tf(rb[t].w)};
        *(uint4*)(sm + AW + w) = ub;
    }
    __syncthreads();

    const int NS = C_ / KC;
    int buf = 0;
    for (int s = 0; s < NS; s++) {
        if (s + 1 < NS) {
            int kc = (s + 1) * KC;
            #pragma unroll
            for (int t = 0; t < 4; t++) {
                int r = lrow + t * 32;
                ra[t] = *(const float4*)(A + (size_t)(bm + r) * C_ + kc + lcol);
                rb[t] = *(const float4*)(W + (size_t)(bn + r) * C_ + kc + lcol);
            }
        }
        unsigned abase = sbase + (unsigned)(buf * 2 * AW) * 4u;
        unsigned bbase = abase + (unsigned)AW * 4u;
        #pragma unroll
        for (int ks = 0; ks < 4; ks++) {
            int k0 = ks * 8;
            unsigned af[4][4], bf[2][4];
            #pragma unroll
            for (int i = 0; i < 4; i++) {
                int r = wm * 64 + i * 16 + arow_l;
                ldsm4(af[i], abase + gswz(r, k0 + acol_l) * 4u);
            }
            #pragma unroll
            for (int jp = 0; jp < 2; jp++) {
                int r = wn * 32 + jp * 16 + brow_l;
                ldsm4(bf[jp], bbase + gswz(r, k0 + bcol_l) * 4u);
            }
            #pragma unroll
            for (int i = 0; i < 4; i++) {
                mma8(acc[i][0], af[i], &bf[0][0]);
                mma8(acc[i][1], af[i], &bf[0][2]);
                mma8(acc[i][2], af[i], &bf[1][0]);
                mma8(acc[i][3], af[i], &bf[1][2]);
            }
        }
        if (s + 1 < NS) {
            float* dst = sm + (buf ^ 1) * 2 * AW;
            #pragma unroll
            for (int t = 0; t < 4; t++) {
                int r = lrow + t * 32;
                unsigned w = gswz(r, lcol);
                uint4 ua = {f2tf(ra[t].x), f2tf(ra[t].y), f2tf(ra[t].z), f2tf(ra[t].w)};
                *(uint4*)(dst + w) = ua;
                uint4 ub = {f2tf(rb[t].x), f2tf(rb[t].y), f2tf(rb[t].z), f2tf(rb[t].w)};
                *(uint4*)(dst + AW + w) = ub;
            }
        }
        __syncthreads();
        buf ^= 1;
    }
}

// ---------------------------------------------------------------------------
// GEMM 1: qkv = x @ qkv_w^T, scattered into Q/K/V [B,H,N,D]
// ---------------------------------------------------------------------------
__global__ __launch_bounds__(256, 2) void qkv_gemm(const float* __restrict__ A,
                                                   const float* __restrict__ W)
{
    extern __shared__ float sm[];
    int bm = blockIdx.y * 128, bn = blockIdx.x * 128;
    float acc[4][4][4];
    #pragma unroll
    for (int i = 0; i < 4; i++)
        #pragma unroll
        for (int j = 0; j < 4; j++)
            #pragma unroll
            for (int q = 0; q < 4; q++) acc[i][j][q] = 0.f;

    gemm128(A, W, bm, bn, acc, sm);

    int tid = threadIdx.x, wid = tid >> 5, lane = tid & 31;
    int wm = wid >> 2, wn = wid & 3;
    int g = lane >> 2, tg = lane & 3;

    #pragma unroll
    for (int i = 0; i < 4; i++) {
        #pragma unroll
        for (int j = 0; j < 4; j++) {
            int col = bn + wn * 32 + j * 8 + 2 * tg;
            int three = col >> 10, rem = col & 1023;
            int h = rem >> 6, d = rem & 63;
            float* dst = (three == 0) ? g_q : (three == 1 ? g_k : g_v);
            #pragma unroll
            for (int half = 0; half < 2; half++) {
                int row = bm + wm * 64 + i * 16 + g + half * 8;
                int b = row >> 11, n = row & (N_ - 1);
                float2 v = {acc[i][j][half * 2], acc[i][j][half * 2 + 1]};
                *(float2*)(dst + (((size_t)b * H_ + h) * N_ + n) * D_ + d) = v;
            }
        }
    }
}

// ---------------------------------------------------------------------------
// GEMM 2: out = g_att @ proj_w^T + proj_b
// ---------------------------------------------------------------------------
__global__ __launch_bounds__(256, 2) void proj_gemm(const float* __restrict__ W,
                                                    const float* __restrict__ bias,
                                                    float* __restrict__ out)
{
    extern __shared__ float sm[];
    int bm = blockIdx.y * 128, bn = blockIdx.x * 128;
    float acc[4][4][4];
    #pragma unroll
    for (int i = 0; i < 4; i++)
        #pragma unroll
        for (int j = 0; j < 4; j++)
            #pragma unroll
            for (int q = 0; q < 4; q++) acc[i][j][q] = 0.f;

    gemm128(g_att, W, bm, bn, acc, sm);

    int tid = threadIdx.x, wid = tid >> 5, lane = tid & 31;
    int wm = wid >> 2, wn = wid & 3;
    int g = lane >> 2, tg = lane & 3;

    #pragma unroll
    for (int i = 0; i < 4; i++) {
        #pragma unroll
        for (int j = 0; j < 4; j++) {
            int col = bn + wn * 32 + j * 8 + 2 * tg;
            float b0 = bias[col], b1 = bias[col + 1];
            #pragma unroll
            for (int half = 0; half < 2; half++) {
                int row = bm + wm * 64 + i * 16 + g + half * 8;
                float2 v = {acc[i][j][half * 2] + b0, acc[i][j][half * 2 + 1] + b1};
                *(float2*)(out + (size_t)row * C_ + col) = v;
            }
        }
    }
}

// ---------------------------------------------------------------------------
// Causal flash attention, tf32 MMA. Block = (qtile 128 rows, head, batch),
// 4 warps x 32 q-rows. ldmatrix for Q/K/P fragments, scalar LDS for V.
// Softmax in exp2 domain. Pitch-64 XOR-swizzled smem.
// ---------------------------------------------------------------------------
__device__ __forceinline__ unsigned aswz(int row, int col) {   // word idx
    return (unsigned)(row * 64 + ((((col >> 2) ^ (row & 7)) << 2) | (col & 3)));
}

#define QS_OFF 0
#define KS_OFF (128*64)
#define VS_OFF (KS_OFF + 64*64)
#define SS_OFF (VS_OFF + 64*64)
#define ATT_SMEM ((SS_OFF + 128*64) * 4)

__global__ __launch_bounds__(128) void attn_kernel()
{
    extern __shared__ float sm[];
    unsigned sbase = (unsigned)__cvta_generic_to_shared(sm);

    int qt = (int)(gridDim.x - 1 - blockIdx.x);   // heavy tiles first
    int hh = blockIdx.y, b = blockIdx.z;
    int tid = threadIdx.x, w = tid >> 5, lane = tid & 31;
    int g = lane >> 2, tg = lane & 3;
    int wr = w * 32;

    int arow_l = (lane & 7) + (((lane >> 3) & 1) << 3);
    int acol_l = (lane >> 4) << 2;
    int brow_l = (lane & 7) + (((lane >> 4) & 1) << 3);
    int bcol_l = ((lane >> 3) & 1) << 2;

    const float* Qg = g_q + ((size_t)b * H_ + hh) * N_ * D_;
    const float* Kg = g_k + ((size_t)b * H_ + hh) * N_ * D_;
    const float* Vg = g_v + ((size_t)b * H_ + hh) * N_ * D_;

    const float SC2 = 0.125f * 1.44269504088896f;  // scale * log2(e)

    // Load Q tile (scaled + tf32-rounded) — 128 rows x 64 cols = 2048 float4s
    #pragma unroll
    for (int t = 0; t < 16; t++) {
        int idx = tid + t * 128;
        int r = idx >> 4, c4 = (idx & 15) * 4;
        float4 v = *(const float4*)(Qg + (size_t)(qt * 128 + r) * D_ + c4);
        uint4 u = {f2tf(v.x * SC2), f2tf(v.y * SC2), f2tf(v.z * SC2), f2tf(v.w * SC2)};
        *(uint4*)(sm + QS_OFF + aswz(r, c4)) = u;
    }

    float o[2][8][4];
    #pragma unroll
    for (int i = 0; i < 2; i++)
        #pragma unroll
        for (int nt = 0; nt < 8; nt++)
            #pragma unroll
            for (int q = 0; q < 4; q++) o[i][nt][q] = 0.f;
    float mrow[2][2], lrow[2][2];
    #pragma unroll
    for (int i = 0; i < 2; i++) { mrow[i][0] = mrow[i][1] = -1e30f; lrow[i][0] = lrow[i][1] = 0.f; }

    int nkt = 2 * qt + 2;
    for (int kt = 0; kt < nkt; kt++) {
        __syncthreads();
        // Load K, V tiles (64x64, tf32)
        #pragma unroll
        for (int t = 0; t < 8; t++) {
            int idx = tid + t * 128;
            int r = idx >> 4, c4 = (idx & 15) * 4;
            float4 kv = *(const float4*)(Kg + (size_t)(kt * 64 + r) * D_ + c4);
            uint4 uk = {f2tf(kv.x), f2tf(kv.y), f2tf(kv.z), f2tf(kv.w)};
            *(uint4*)(sm + KS_OFF + aswz(r, c4)) = uk;
            float4 vv = *(const float4*)(Vg + (size_t)(kt * 64 + r) * D_ + c4);
            uint4 uv = {f2tf(vv.x), f2tf(vv.y), f2tf(vv.z), f2tf(vv.w)};
            *(uint4*)(sm + VS_OFF + aswz(r, c4)) = uv;
        }
        __syncthreads();

        // per-warp causal skip: no key in this tile is <= warp's max row
        if (kt * 64 > qt * 128 + wr + 31) continue;

        // S = Q K^T  (both 16-row halves i=0,1; K frags shared)
        float s[2][8][4];
        #pragma unroll
        for (int i = 0; i < 2; i++)
            #pragma unroll
            for (int nt = 0; nt < 8; nt++)
                #pragma unroll
                for (int q = 0; q < 4; q++) s[i][nt][q] = 0.f;

        unsigned qbase = sbase + QS_OFF * 4u;
        unsigned kbase = sbase + KS_OFF * 4u;
        #pragma unroll
        for (int ks = 0; ks < 8; ks++) {
            int k0 = ks * 8;
            unsigned kf[4][4];
            #pragma unroll
            for (int jp = 0; jp < 4; jp++)
                ldsm4(kf[jp], kbase + aswz(jp * 16 + brow_l, k0 + bcol_l) * 4u);
            #pragma unroll
            for (int i = 0; i < 2; i++) {
                unsigned af[4];
                ldsm4(af, qbase + aswz(wr + i * 16 + arow_l, k0 + acol_l) * 4u);
                #pragma unroll
                for (int jp = 0; jp < 4; jp++) {
                    mma8(s[i][2 * jp],     af, &kf[jp][0]);
                    mma8(s[i][2 * jp + 1], af, &kf[jp][2]);
                }
            }
        }

        // causal mask (only tiles straddling the diagonal)
        if (kt * 64 + 63 > qt * 128 + wr) {
            #pragma unroll
            for (int i = 0; i < 2; i++) {
                int row0 = qt * 128 + wr + i * 16 + g;
                #pragma unroll
                for (int nt = 0; nt < 8; nt++) {
                    int c0 = kt * 64 + nt * 8 + 2 * tg;
                    if (c0 > row0)         s[i][nt][0] = -1e30f;
                    if (c0 + 1 > row0)     s[i][nt][1] = -1e30f;
                    if (c0 > row0 + 8)     s[i][nt][2] = -1e30f;
                    if (c0 + 1 > row0 + 8) s[i][nt][3] = -1e30f;
                }
            }
        }

        // online softmax (exp2 domain) + P store
        #pragma unroll
        for (int i = 0; i < 2; i++) {
            float mx0 = -1e30f, mx1 = -1e30f;
            #pragma unroll
            for (int nt = 0; nt < 8; nt++) {
                mx0 = fmaxf(mx0, fmaxf(s[i][nt][0], s[i][nt][1]));
                mx1 = fmaxf(mx1, fmaxf(s[i][nt][2], s[i][nt][3]));
            }
            mx0 = fmaxf(mx0, __shfl_xor_sync(0xffffffffu, mx0, 1));
            mx0 = fmaxf(mx0, __shfl_xor_sync(0xffffffffu, mx0, 2));
            mx1 = fmaxf(mx1, __shfl_xor_sync(0xffffffffu, mx1, 1));
            mx1 = fmaxf(mx1, __shfl_xor_sync(0xffffffffu, mx1, 2));

            float nm0 = fmaxf(mrow[i][0], mx0), nm1 = fmaxf(mrow[i][1], mx1);
            float a0 = exp2f(mrow[i][0] - nm0), a1 = exp2f(mrow[i][1] - nm1);
            mrow[i][0] = nm0; mrow[i][1] = nm1;

            int r0 = wr + i * 16 + g;
            float ls0 = 0.f, ls1 = 0.f;
            #pragma unroll
            for (int nt = 0; nt < 8; nt++) {
                float p0 = exp2f(s[i][nt][0] - nm0);
                float p1 = exp2f(s[i][nt][1] - nm0);
                float p2 = exp2f(s[i][nt][2] - nm1);
                float p3 = exp2f(s[i][nt][3] - nm1);
                ls0 += p0 + p1; ls1 += p2 + p3;
                int c0 = nt * 8 + 2 * tg;
                float2 v0 = {__uint_as_float(f2tf(p0)), __uint_as_float(f2tf(p1))};
                *(float2*)(sm + SS_OFF + aswz(r0, c0)) = v0;
                float2 v1 = {__uint_as_float(f2tf(p2)), __uint_as_float(f2tf(p3))};
                *(float2*)(sm + SS_OFF + aswz(r0 + 8, c0)) = v1;
            }
            ls0 += __shfl_xor_sync(0xffffffffu, ls0, 1);
            ls0 += __shfl_xor_sync(0xffffffffu, ls0, 2);
            ls1 += __shfl_xor_sync(0xffffffffu, ls1, 1);
            ls1 += __shfl_xor_sync(0xffffffffu, ls1, 2);
            lrow[i][0] = lrow[i][0] * a0 + ls0;
            lrow[i][1] = lrow[i][1] * a1 + ls1;

            #pragma unroll
            for (int nt = 0; nt < 8; nt++) {
                o[i][nt][0] *= a0; o[i][nt][1] *= a0;
                o[i][nt][2] *= a1; o[i][nt][3] *= a1;
            }
        }
        __syncwarp();

        // O += P V  (P via ldmatrix, V via scalar LDS)
        unsigned pbase = sbase + SS_OFF * 4u;
        #pragma unroll
        for (int ks = 0; ks < 8; ks++) {
            int k0 = ks * 8;
            unsigned vb[8][2];
            #pragma unroll
            for (int nt = 0; nt < 8; nt++) {
                int n = nt * 8 + g;
                vb[nt][0] = __float_as_uint(sm[VS_OFF + aswz(k0 + tg, n)]);
                vb[nt][1] = __float_as_uint(sm[VS_OFF + aswz(k0 + tg + 4, n)]);
            }
            #pragma unroll
            for (int i = 0; i < 2; i++) {
                unsigned pf[4];
                ldsm4(pf, pbase + aswz(wr + i * 16 + arow_l, k0 + acol_l) * 4u);
                #pragma unroll
                for (int nt = 0; nt < 8; nt++)
                    mma8(o[i][nt], pf, vb[nt]);
            }
        }
    }

    // epilogue: normalize + write [B,N,C]
    float* Og = g_att + (size_t)b * N_ * C_ + (size_t)hh * 64;
    #pragma unroll
    for (int i = 0; i < 2; i++) {
        #pragma unroll
        for (int half = 0; half < 2; half++) {
            float inv = 1.f / lrow[i][half];
            int row = qt * 128 + wr + i * 16 + g + half * 8;
            #pragma unroll
            for (int nt = 0; nt < 8; nt++) {
                int d = nt * 8 + 2 * tg;
                float2 v = {o[i][nt][half * 2] * inv, o[i][nt][half * 2 + 1] * inv};
                *(float2*)(Og + (size_t)row * C_ + d) = v;
            }
        }
    }
}

// ---------------------------------------------------------------------------
extern "C" void kernel_launch(void* const* d_in, const int* in_sizes, int n_in,
                              void* d_out, int out_size)
{
    const float* x      = (const float*)d_in[0];
    const float* qkv_w  = (const float*)d_in[1];
    const float* proj_w = (const float*)d_in[2];
    const float* proj_b = (const float*)d_in[3];
    float* out = (float*)d_out;

    int gsmem = 4 * AW * (int)sizeof(float);   // 65536 B
    cudaFuncSetAttribute(qkv_gemm, cudaFuncAttributeMaxDynamicSharedMemorySize, gsmem);
    cudaFuncSetAttribute(proj_gemm, cudaFuncAttributeMaxDynamicSharedMemorySize, gsmem);
    cudaFuncSetAttribute(attn_kernel, cudaFuncAttributeMaxDynamicSharedMemorySize, ATT_SMEM);

    qkv_gemm<<<dim3(24, 64), 256, gsmem>>>(x, qkv_w);
    attn_kernel<<<dim3(N_ / 128, H_, B_), 128, ATT_SMEM>>>();
    proj_gemm<<<dim3(8, 64), 256, gsmem>>>(proj_w, proj_b, out);
}

// round 6
// speedup vs baseline: 4.3156x; 1.0467x over previous
#include <cuda_runtime.h>

#define B_ 4
#define N_ 2048
#define C_ 1024
#define H_ 16
#define D_ 64

// Scratch (device globals — no runtime allocation allowed)
__device__ float g_q[(size_t)B_*H_*N_*D_];
__device__ float g_k[(size_t)B_*H_*N_*D_];
__device__ float g_v[(size_t)B_*H_*N_*D_];
__device__ float g_att[(size_t)B_*N_*C_];

__device__ __forceinline__ unsigned f2tf(float x) {
    unsigned u; asm("cvt.rna.tf32.f32 %0, %1;" : "=r"(u) : "f"(x)); return u;
}
__device__ __forceinline__ void mma8(float* c, const unsigned* a, const unsigned* b) {
    asm volatile("mma.sync.aligned.m16n8k8.row.col.f32.tf32.tf32.f32 "
        "{%0,%1,%2,%3}, {%4,%5,%6,%7}, {%8,%9}, {%0,%1,%2,%3};"
        : "+f"(c[0]), "+f"(c[1]), "+f"(c[2]), "+f"(c[3])
        : "r"(a[0]), "r"(a[1]), "r"(a[2]), "r"(a[3]), "r"(b[0]), "r"(b[1]));
}
__device__ __forceinline__ void ldsm4(unsigned* r, unsigned addr) {
    asm volatile("ldmatrix.sync.aligned.m8n8.x4.shared.b16 {%0,%1,%2,%3}, [%4];"
        : "=r"(r[0]), "=r"(r[1]), "=r"(r[2]), "=r"(r[3]) : "r"(addr));
}
__device__ __forceinline__ uint4 cvt4(float4 v) {
    uint4 u = {f2tf(v.x), f2tf(v.y), f2tf(v.z), f2tf(v.w)};
    return u;
}

// ---------------------------------------------------------------------------
// GEMM core: C_tile[128x128] = A[128xK] * W[128xK]^T, K=1024, tf32 MMA.
// 128 threads, 4 warps (2x2), warp tile 64x64. KC=32, double buffer,
// staged LDG/STS interleaved into the 4 k-steps.
// ---------------------------------------------------------------------------
#define KC 32
#define AW (128*KC)   // words per matrix per buffer

__device__ __forceinline__ unsigned gswz(int row, int col) {  // word idx, col%4==0
    return (unsigned)(row * KC + ((((col >> 2) ^ (row & 7)) << 2)));
}

#define KSTEP(ks)                                                           \
    {                                                                       \
        int k0 = (ks) * 8;                                                  \
        unsigned af[4][4], bf[4][4];                                        \
        _Pragma("unroll")                                                   \
        for (int i = 0; i < 4; i++) {                                       \
            int r = wm * 64 + i * 16 + arow_l;                              \
            ldsm4(af[i], abase + gswz(r, k0 + acol_l) * 4u);                \
        }                                                                   \
        _Pragma("unroll")                                                   \
        for (int jp = 0; jp < 4; jp++) {                                    \
            int r = wn * 64 + jp * 16 + brow_l;                             \
            ldsm4(bf[jp], bbase + gswz(r, k0 + bcol_l) * 4u);               \
        }                                                                   \
        _Pragma("unroll")                                                   \
        for (int i = 0; i < 4; i++)                                         \
            _Pragma("unroll")                                               \
            for (int jp = 0; jp < 4; jp++) {                                \
                mma8(acc[i][2*jp],   af[i], &bf[jp][0]);                    \
                mma8(acc[i][2*jp+1], af[i], &bf[jp][2]);                    \
            }                                                               \
    }

__device__ __forceinline__ void gemm128(const float* __restrict__ A,
                                        const float* __restrict__ W,
                                        int bm, int bn,
                                        float acc[4][8][4], float* sm)
{
    int tid = threadIdx.x, wid = tid >> 5, lane = tid & 31;
    int wm = wid >> 1, wn = wid & 1;
    unsigned sbase = (unsigned)__cvta_generic_to_shared(sm);

    int lrow = tid >> 3;            // 0..15 (+16 per t, 8 t's)
    int lcol = (tid & 7) * 4;

    int arow_l = (lane & 7) + (((lane >> 3) & 1) << 3);
    int acol_l = (lane >> 4) << 2;
    int brow_l = (lane & 7) + (((lane >> 4) & 1) << 3);
    int bcol_l = ((lane >> 3) & 1) << 2;

    float4 st[8];
    // prologue: stage 0 -> buffer 0
    #pragma unroll
    for (int t = 0; t < 8; t++)
        st[t] = *(const float4*)(A + (size_t)(bm + lrow + t * 16) * C_ + lcol);
    #pragma unroll
    for (int t = 0; t < 8; t++)
        *(uint4*)(sm + gswz(lrow + t * 16, lcol)) = cvt4(st[t]);
    #pragma unroll
    for (int t = 0; t < 8; t++)
        st[t] = *(const float4*)(W + (size_t)(bn + lrow + t * 16) * C_ + lcol);
    #pragma unroll
    for (int t = 0; t < 8; t++)
        *(uint4*)(sm + AW + gswz(lrow + t * 16, lcol)) = cvt4(st[t]);
    __syncthreads();

    const int NS = C_ / KC;
    int buf = 0;
    for (int s = 0; s < NS; s++) {
        bool more = (s + 1 < NS);
        int kc = (s + 1) * KC;
        unsigned abase = sbase + (unsigned)(buf * 2 * AW) * 4u;
        unsigned bbase = abase + (unsigned)AW * 4u;
        float* dst = sm + (buf ^ 1) * 2 * AW;

        if (more) {
            #pragma unroll
            for (int t = 0; t < 8; t++)
                st[t] = *(const float4*)(A + (size_t)(bm + lrow + t * 16) * C_ + kc + lcol);
        }
        KSTEP(0)
        KSTEP(1)
        if (more) {
            #pragma unroll
            for (int t = 0; t < 8; t++)
                *(uint4*)(dst + gswz(lrow + t * 16, lcol)) = cvt4(st[t]);
            #pragma unroll
            for (int t = 0; t < 8; t++)
                st[t] = *(const float4*)(W + (size_t)(bn + lrow + t * 16) * C_ + kc + lcol);
        }
        KSTEP(2)
        KSTEP(3)
        if (more) {
            #pragma unroll
            for (int t = 0; t < 8; t++)
                *(uint4*)(dst + AW + gswz(lrow + t * 16, lcol)) = cvt4(st[t]);
        }
        __syncthreads();
        buf ^= 1;
    }
}

// ---------------------------------------------------------------------------
// GEMM 1: qkv = x @ qkv_w^T, scattered into Q/K/V [B,H,N,D]
// ---------------------------------------------------------------------------
__global__ __launch_bounds__(128, 2) void qkv_gemm(const float* __restrict__ A,
                                                   const float* __restrict__ W)
{
    extern __shared__ float sm[];
    int bm = blockIdx.y * 128, bn = blockIdx.x * 128;
    float acc[4][8][4];
    #pragma unroll
    for (int i = 0; i < 4; i++)
        #pragma unroll
        for (int j = 0; j < 8; j++)
            #pragma unroll
            for (int q = 0; q < 4; q++) acc[i][j][q] = 0.f;

    gemm128(A, W, bm, bn, acc, sm);

    int tid = threadIdx.x, wid = tid >> 5, lane = tid & 31;
    int wm = wid >> 1, wn = wid & 1;
    int g = lane >> 2, tg = lane & 3;

    #pragma unroll
    for (int i = 0; i < 4; i++) {
        #pragma unroll
        for (int j = 0; j < 8; j++) {
            int col = bn + wn * 64 + j * 8 + 2 * tg;
            int three = col >> 10, rem = col & 1023;
            int h = rem >> 6, d = rem & 63;
            float* dst = (three == 0) ? g_q : (three == 1 ? g_k : g_v);
            #pragma unroll
            for (int half = 0; half < 2; half++) {
                int row = bm + wm * 64 + i * 16 + g + half * 8;
                int b = row >> 11, n = row & (N_ - 1);
                float2 v = {acc[i][j][half * 2], acc[i][j][half * 2 + 1]};
                *(float2*)(dst + (((size_t)b * H_ + h) * N_ + n) * D_ + d) = v;
            }
        }
    }
}

// ---------------------------------------------------------------------------
// GEMM 2: out = g_att @ proj_w^T + proj_b
// ---------------------------------------------------------------------------
__global__ __launch_bounds__(128, 2) void proj_gemm(const float* __restrict__ W,
                                                    const float* __restrict__ bias,
                                                    float* __restrict__ out)
{
    extern __shared__ float sm[];
    int bm = blockIdx.y * 128, bn = blockIdx.x * 128;
    float acc[4][8][4];
    #pragma unroll
    for (int i = 0; i < 4; i++)
        #pragma unroll
        for (int j = 0; j < 8; j++)
            #pragma unroll
            for (int q = 0; q < 4; q++) acc[i][j][q] = 0.f;

    gemm128(g_att, W, bm, bn, acc, sm);

    int tid = threadIdx.x, wid = tid >> 5, lane = tid & 31;
    int wm = wid >> 1, wn = wid & 1;
    int g = lane >> 2, tg = lane & 3;

    #pragma unroll
    for (int i = 0; i < 4; i++) {
        #pragma unroll
        for (int j = 0; j < 8; j++) {
            int col = bn + wn * 64 + j * 8 + 2 * tg;
            float b0 = bias[col], b1 = bias[col + 1];
            #pragma unroll
            for (int half = 0; half < 2; half++) {
                int row = bm + wm * 64 + i * 16 + g + half * 8;
                float2 v = {acc[i][j][half * 2] + b0, acc[i][j][half * 2 + 1] + b1};
                *(float2*)(out + (size_t)row * C_ + col) = v;
            }
        }
    }
}

// ---------------------------------------------------------------------------
// Causal flash attention, tf32 MMA. Block = (qtile 128 rows, head, batch),
// 4 warps x 32 q-rows. ldmatrix for Q/K/P fragments, scalar LDS for V.
// K prefetched one tile ahead into registers; V load overlapped with QK.
// ---------------------------------------------------------------------------
__device__ __forceinline__ unsigned aswz(int row, int col) {   // word idx
    return (unsigned)(row * 64 + ((((col >> 2) ^ (row & 7)) << 2) | (col & 3)));
}

#define QS_OFF 0
#define KS_OFF (128*64)
#define VS_OFF (KS_OFF + 64*64)
#define SS_OFF (VS_OFF + 64*64)
#define ATT_SMEM ((SS_OFF + 128*64) * 4)

__global__ __launch_bounds__(128) void attn_kernel()
{
    extern __shared__ float sm[];
    unsigned sbase = (unsigned)__cvta_generic_to_shared(sm);

    int qt = (int)(gridDim.x - 1 - blockIdx.x);   // heavy tiles first
    int hh = blockIdx.y, b = blockIdx.z;
    int tid = threadIdx.x, w = tid >> 5, lane = tid & 31;
    int g = lane >> 2, tg = lane & 3;
    int wr = w * 32;

    int arow_l = (lane & 7) + (((lane >> 3) & 1) << 3);
    int acol_l = (lane >> 4) << 2;
    int brow_l = (lane & 7) + (((lane >> 4) & 1) << 3);
    int bcol_l = ((lane >> 3) & 1) << 2;

    const float* Qg = g_q + ((size_t)b * H_ + hh) * N_ * D_;
    const float* Kg = g_k + ((size_t)b * H_ + hh) * N_ * D_;
    const float* Vg = g_v + ((size_t)b * H_ + hh) * N_ * D_;

    const float SC2 = 0.125f * 1.44269504088896f;  // scale * log2(e)

    int lr = tid >> 4, lc4 = (tid & 15) * 4;       // tile loader: +8 rows per t

    // Load Q tile (scaled + tf32-rounded) — 128 rows x 64 cols
    #pragma unroll
    for (int t = 0; t < 16; t++) {
        int r = lr + t * 8;
        float4 v = *(const float4*)(Qg + (size_t)(qt * 128 + r) * D_ + lc4);
        uint4 u = {f2tf(v.x * SC2), f2tf(v.y * SC2), f2tf(v.z * SC2), f2tf(v.w * SC2)};
        *(uint4*)(sm + QS_OFF + aswz(r, lc4)) = u;
    }

    float o[2][8][4];
    #pragma unroll
    for (int i = 0; i < 2; i++)
        #pragma unroll
        for (int nt = 0; nt < 8; nt++)
            #pragma unroll
            for (int q = 0; q < 4; q++) o[i][nt][q] = 0.f;
    float mrow[2][2], lrow_[2][2];
    #pragma unroll
    for (int i = 0; i < 2; i++) { mrow[i][0] = mrow[i][1] = -1e30f; lrow_[i][0] = lrow_[i][1] = 0.f; }

    // Prefetch K tile 0 into registers
    float4 kreg[8];
    #pragma unroll
    for (int t = 0; t < 8; t++)
        kreg[t] = *(const float4*)(Kg + (size_t)(lr + t * 8) * D_ + lc4);

    int nkt = 2 * qt + 2;
    for (int kt = 0; kt < nkt; kt++) {
        __syncthreads();                 // prior tile's smem reads complete
        // STS K (cvt) from prefetched regs
        #pragma unroll
        for (int t = 0; t < 8; t++)
            *(uint4*)(sm + KS_OFF + aswz(lr + t * 8, lc4)) = cvt4(kreg[t]);
        // Issue V load for this tile (consumed after softmax)
        float4 vreg[8];
        #pragma unroll
        for (int t = 0; t < 8; t++)
            vreg[t] = *(const float4*)(Vg + (size_t)(kt * 64 + lr + t * 8) * D_ + lc4);
        __syncthreads();                 // K visible

        bool active = !(kt * 64 > qt * 128 + wr + 31);

        if (active) {
            // S = Q K^T
            float s[2][8][4];
            #pragma unroll
            for (int i = 0; i < 2; i++)
                #pragma unroll
                for (int nt = 0; nt < 8; nt++)
                    #pragma unroll
                    for (int q = 0; q < 4; q++) s[i][nt][q] = 0.f;

            unsigned qbase = sbase + QS_OFF * 4u;
            unsigned kbase = sbase + KS_OFF * 4u;
            #pragma unroll
            for (int ks = 0; ks < 8; ks++) {
                int k0 = ks * 8;
                unsigned kf[4][4];
                #pragma unroll
                for (int jp = 0; jp < 4; jp++)
                    ldsm4(kf[jp], kbase + aswz(jp * 16 + brow_l, k0 + bcol_l) * 4u);
                #pragma unroll
                for (int i = 0; i < 2; i++) {
                    unsigned af[4];
                    ldsm4(af, qbase + aswz(wr + i * 16 + arow_l, k0 + acol_l) * 4u);
                    #pragma unroll
                    for (int jp = 0; jp < 4; jp++) {
                        mma8(s[i][2 * jp],     af, &kf[jp][0]);
                        mma8(s[i][2 * jp + 1], af, &kf[jp][2]);
                    }
                }
            }

            // causal mask (tiles straddling the diagonal)
            if (kt * 64 + 63 > qt * 128 + wr) {
                #pragma unroll
                for (int i = 0; i < 2; i++) {
                    int row0 = qt * 128 + wr + i * 16 + g;
                    #pragma unroll
                    for (int nt = 0; nt < 8; nt++) {
                        int c0 = kt * 64 + nt * 8 + 2 * tg;
                        if (c0 > row0)         s[i][nt][0] = -1e30f;
                        if (c0 + 1 > row0)     s[i][nt][1] = -1e30f;
                        if (c0 > row0 + 8)     s[i][nt][2] = -1e30f;
                        if (c0 + 1 > row0 + 8) s[i][nt][3] = -1e30f;
                    }
                }
            }

            // online softmax (exp2 domain) + P store
            #pragma unroll
            for (int i = 0; i < 2; i++) {
                float mx0 = -1e30f, mx1 = -1e30f;
                #pragma unroll
                for (int nt = 0; nt < 8; nt++) {
                    mx0 = fmaxf(mx0, fmaxf(s[i][nt][0], s[i][nt][1]));
                    mx1 = fmaxf(mx1, fmaxf(s[i][nt][2], s[i][nt][3]));
                }
                mx0 = fmaxf(mx0, __shfl_xor_sync(0xffffffffu, mx0, 1));
                mx0 = fmaxf(mx0, __shfl_xor_sync(0xffffffffu, mx0, 2));
                mx1 = fmaxf(mx1, __shfl_xor_sync(0xffffffffu, mx1, 1));
                mx1 = fmaxf(mx1, __shfl_xor_sync(0xffffffffu, mx1, 2));

                float nm0 = fmaxf(mrow[i][0], mx0), nm1 = fmaxf(mrow[i][1], mx1);
                float a0 = exp2f(mrow[i][0] - nm0), a1 = exp2f(mrow[i][1] - nm1);
                mrow[i][0] = nm0; mrow[i][1] = nm1;

                int r0 = wr + i * 16 + g;
                float ls0 = 0.f, ls1 = 0.f;
                #pragma unroll
                for (int nt = 0; nt < 8; nt++) {
                    float p0 = exp2f(s[i][nt][0] - nm0);
                    float p1 = exp2f(s[i][nt][1] - nm0);
                    float p2 = exp2f(s[i][nt][2] - nm1);
                    float p3 = exp2f(s[i][nt][3] - nm1);
                    ls0 += p0 + p1; ls1 += p2 + p3;
                    int c0 = nt * 8 + 2 * tg;
                    float2 v0 = {__uint_as_float(f2tf(p0)), __uint_as_float(f2tf(p1))};
                    *(float2*)(sm + SS_OFF + aswz(r0, c0)) = v0;
                    float2 v1 = {__uint_as_float(f2tf(p2)), __uint_as_float(f2tf(p3))};
                    *(float2*)(sm + SS_OFF + aswz(r0 + 8, c0)) = v1;
                }
                ls0 += __shfl_xor_sync(0xffffffffu, ls0, 1);
                ls0 += __shfl_xor_sync(0xffffffffu, ls0, 2);
                ls1 += __shfl_xor_sync(0xffffffffu, ls1, 1);
                ls1 += __shfl_xor_sync(0xffffffffu, ls1, 2);
                lrow_[i][0] = lrow_[i][0] * a0 + ls0;
                lrow_[i][1] = lrow_[i][1] * a1 + ls1;

                #pragma unroll
                for (int nt = 0; nt < 8; nt++) {
                    o[i][nt][0] *= a0; o[i][nt][1] *= a0;
                    o[i][nt][2] *= a1; o[i][nt][3] *= a1;
                }
            }
            __syncwarp();
        }

        // STS V (cvt) — overlapped LDG latency behind QK+softmax
        #pragma unroll
        for (int t = 0; t < 8; t++)
            *(uint4*)(sm + VS_OFF + aswz(lr + t * 8, lc4)) = cvt4(vreg[t]);

        // Prefetch K for next tile (clamped, dummy on last iter)
        int ktn = (kt + 1 < N_ / 64) ? kt + 1 : kt;
        #pragma unroll
        for (int t = 0; t < 8; t++)
            kreg[t] = *(const float4*)(Kg + (size_t)(ktn * 64 + lr + t * 8) * D_ + lc4);

        __syncthreads();                 // V (and P via syncwarp) visible

        if (active) {
            // O += P V  (P via ldmatrix, V via scalar LDS)
            unsigned pbase = sbase + SS_OFF * 4u;
            #pragma unroll
            for (int ks = 0; ks < 8; ks++) {
                int k0 = ks * 8;
                unsigned vb[8][2];
                #pragma unroll
                for (int nt = 0; nt < 8; nt++) {
                    int n = nt * 8 + g;
                    vb[nt][0] = __float_as_uint(sm[VS_OFF + aswz(k0 + tg, n)]);
                    vb[nt][1] = __float_as_uint(sm[VS_OFF + aswz(k0 + tg + 4, n)]);
                }
                #pragma unroll
                for (int i = 0; i < 2; i++) {
                    unsigned pf[4];
                    ldsm4(pf, pbase + aswz(wr + i * 16 + arow_l, k0 + acol_l) * 4u);
                    #pragma unroll
                    for (int nt = 0; nt < 8; nt++)
                        mma8(o[i][nt], pf, vb[nt]);
                }
            }
        }
    }

    // epilogue: normalize + write [B,N,C]
    float* Og = g_att + (size_t)b * N_ * C_ + (size_t)hh * 64;
    #pragma unroll
    for (int i = 0; i < 2; i++) {
        #pragma unroll
        for (int half = 0; half < 2; half++) {
            float inv = 1.f / lrow_[i][half];
            int row = qt * 128 + wr + i * 16 + g + half * 8;
            #pragma unroll
            for (int nt = 0; nt < 8; nt++) {
                int d = nt * 8 + 2 * tg;
                float2 v = {o[i][nt][half * 2] * inv, o[i][nt][half * 2 + 1] * inv};
                *(float2*)(Og + (size_t)row * C_ + d) = v;
            }
        }
    }
}

// ---------------------------------------------------------------------------
extern "C" void kernel_launch(void* const* d_in, const int* in_sizes, int n_in,
                              void* d_out, int out_size)
{
    const float* x      = (const float*)d_in[0];
    const float* qkv_w  = (const float*)d_in[1];
    const float* proj_w = (const float*)d_in[2];
    const float* proj_b = (const float*)d_in[3];
    float* out = (float*)d_out;

    int gsmem = 4 * AW * (int)sizeof(float);   // 65536 B
    cudaFuncSetAttribute(qkv_gemm, cudaFuncAttributeMaxDynamicSharedMemorySize, gsmem);
    cudaFuncSetAttribute(proj_gemm, cudaFuncAttributeMaxDynamicSharedMemorySize, gsmem);
    cudaFuncSetAttribute(attn_kernel, cudaFuncAttributeMaxDynamicSharedMemorySize, ATT_SMEM);

    qkv_gemm<<<dim3(24, 64), 128, gsmem>>>(x, qkv_w);
    attn_kernel<<<dim3(N_ / 128, H_, B_), 128, ATT_SMEM>>>();
    proj_gemm<<<dim3(8, 64), 128, gsmem>>>(proj_w, proj_b, out);
}

// round 8
// speedup vs baseline: 4.4090x; 1.0216x over previous
#include <cuda_runtime.h>

#define B_ 4
#define N_ 2048
#define C_ 1024
#define H_ 16
#define D_ 64

// Scratch (device globals — no runtime allocation allowed)
__device__ float g_q[(size_t)B_*H_*N_*D_];
__device__ float g_k[(size_t)B_*H_*N_*D_];
__device__ float g_v[(size_t)B_*H_*N_*D_];
__device__ float g_att[(size_t)B_*N_*C_];

__device__ __forceinline__ unsigned f2tf(float x) {
    unsigned u; asm("cvt.rna.tf32.f32 %0, %1;" : "=r"(u) : "f"(x)); return u;
}
__device__ __forceinline__ float ex2(float x) {
    float y; asm("ex2.approx.ftz.f32 %0, %1;" : "=f"(y) : "f"(x)); return y;
}
__device__ __forceinline__ void mma8(float* c, const unsigned* a, const unsigned* b) {
    asm volatile("mma.sync.aligned.m16n8k8.row.col.f32.tf32.tf32.f32 "
        "{%0,%1,%2,%3}, {%4,%5,%6,%7}, {%8,%9}, {%0,%1,%2,%3};"
        : "+f"(c[0]), "+f"(c[1]), "+f"(c[2]), "+f"(c[3])
        : "r"(a[0]), "r"(a[1]), "r"(a[2]), "r"(a[3]), "r"(b[0]), "r"(b[1]));
}
__device__ __forceinline__ void ldsm4(unsigned* r, unsigned addr) {
    asm volatile("ldmatrix.sync.aligned.m8n8.x4.shared.b16 {%0,%1,%2,%3}, [%4];"
        : "=r"(r[0]), "=r"(r[1]), "=r"(r[2]), "=r"(r[3]) : "r"(addr));
}
__device__ __forceinline__ uint4 cvt4(float4 v) {
    uint4 u = {f2tf(v.x), f2tf(v.y), f2tf(v.z), f2tf(v.w)};
    return u;
}

// ---------------------------------------------------------------------------
// GEMM core: C_tile[128x128] = A[128xK] * W[128xK]^T, K=1024, tf32 MMA.
// 128 threads, 4 warps (2x2), warp tile 64x64. KC=32, double buffer,
// staged LDG/STS interleaved into the 4 k-steps.  (R6, passing)
// ---------------------------------------------------------------------------
#define KC 32
#define AW (128*KC)   // words per matrix per buffer

__device__ __forceinline__ unsigned gswz(int row, int col) {  // word idx, col%4==0
    return (unsigned)(row * KC + ((((col >> 2) ^ (row & 7)) << 2)));
}

#define KSTEP(ks)                                                           \
    {                                                                       \
        int k0 = (ks) * 8;                                                  \
        unsigned af[4][4], bf[4][4];                                        \
        _Pragma("unroll")                                                   \
        for (int i = 0; i < 4; i++) {                                       \
            int r = wm * 64 + i * 16 + arow_l;                              \
            ldsm4(af[i], abase + gswz(r, k0 + acol_l) * 4u);                \
        }                                                                   \
        _Pragma("unroll")                                                   \
        for (int jp = 0; jp < 4; jp++) {                                    \
            int r = wn * 64 + jp * 16 + brow_l;                             \
            ldsm4(bf[jp], bbase + gswz(r, k0 + bcol_l) * 4u);               \
        }                                                                   \
        _Pragma("unroll")                                                   \
        for (int i = 0; i < 4; i++)                                         \
            _Pragma("unroll")                                               \
            for (int jp = 0; jp < 4; jp++) {                                \
                mma8(acc[i][2*jp],   af[i], &bf[jp][0]);                    \
                mma8(acc[i][2*jp+1], af[i], &bf[jp][2]);                    \
            }                                                               \
    }

__device__ __forceinline__ void gemm128(const float* __restrict__ A,
                                        const float* __restrict__ W,
                                        int bm, int bn,
                                        float acc[4][8][4], float* sm)
{
    int tid = threadIdx.x, wid = tid >> 5, lane = tid & 31;
    int wm = wid >> 1, wn = wid & 1;
    unsigned sbase = (unsigned)__cvta_generic_to_shared(sm);

    int lrow = tid >> 3;            // 0..15 (+16 per t, 8 t's)
    int lcol = (tid & 7) * 4;

    int arow_l = (lane & 7) + (((lane >> 3) & 1) << 3);
    int acol_l = (lane >> 4) << 2;
    int brow_l = (lane & 7) + (((lane >> 4) & 1) << 3);
    int bcol_l = ((lane >> 3) & 1) << 2;

    float4 st[8];
    // prologue: stage 0 -> buffer 0
    #pragma unroll
    for (int t = 0; t < 8; t++)
        st[t] = *(const float4*)(A + (size_t)(bm + lrow + t * 16) * C_ + lcol);
    #pragma unroll
    for (int t = 0; t < 8; t++)
        *(uint4*)(sm + gswz(lrow + t * 16, lcol)) = cvt4(st[t]);
    #pragma unroll
    for (int t = 0; t < 8; t++)
        st[t] = *(const float4*)(W + (size_t)(bn + lrow + t * 16) * C_ + lcol);
    #pragma unroll
    for (int t = 0; t < 8; t++)
        *(uint4*)(sm + AW + gswz(lrow + t * 16, lcol)) = cvt4(st[t]);
    __syncthreads();

    const int NS = C_ / KC;
    int buf = 0;
    for (int s = 0; s < NS; s++) {
        bool more = (s + 1 < NS);
        int kc = (s + 1) * KC;
        unsigned abase = sbase + (unsigned)(buf * 2 * AW) * 4u;
        unsigned bbase = abase + (unsigned)AW * 4u;
        float* dst = sm + (buf ^ 1) * 2 * AW;

        if (more) {
            #pragma unroll
            for (int t = 0; t < 8; t++)
                st[t] = *(const float4*)(A + (size_t)(bm + lrow + t * 16) * C_ + kc + lcol);
        }
        KSTEP(0)
        KSTEP(1)
        if (more) {
            #pragma unroll
            for (int t = 0; t < 8; t++)
                *(uint4*)(dst + gswz(lrow + t * 16, lcol)) = cvt4(st[t]);
            #pragma unroll
            for (int t = 0; t < 8; t++)
                st[t] = *(const float4*)(W + (size_t)(bn + lrow + t * 16) * C_ + kc + lcol);
        }
        KSTEP(2)
        KSTEP(3)
        if (more) {
            #pragma unroll
            for (int t = 0; t < 8; t++)
                *(uint4*)(dst + AW + gswz(lrow + t * 16, lcol)) = cvt4(st[t]);
        }
        __syncthreads();
        buf ^= 1;
    }
}

// ---------------------------------------------------------------------------
// GEMM 1: qkv = x @ qkv_w^T, scattered into Q/K/V [B,H,N,D]
// ---------------------------------------------------------------------------
__global__ __launch_bounds__(128, 2) void qkv_gemm(const float* __restrict__ A,
                                                   const float* __restrict__ W)
{
    extern __shared__ float sm[];
    int bm = blockIdx.y * 128, bn = blockIdx.x * 128;
    float acc[4][8][4];
    #pragma unroll
    for (int i = 0; i < 4; i++)
        #pragma unroll
        for (int j = 0; j < 8; j++)
            #pragma unroll
            for (int q = 0; q < 4; q++) acc[i][j][q] = 0.f;

    gemm128(A, W, bm, bn, acc, sm);

    int tid = threadIdx.x, wid = tid >> 5, lane = tid & 31;
    int wm = wid >> 1, wn = wid & 1;
    int g = lane >> 2, tg = lane & 3;

    #pragma unroll
    for (int i = 0; i < 4; i++) {
        #pragma unroll
        for (int j = 0; j < 8; j++) {
            int col = bn + wn * 64 + j * 8 + 2 * tg;
            int three = col >> 10, rem = col & 1023;
            int h = rem >> 6, d = rem & 63;
            float* dst = (three == 0) ? g_q : (three == 1 ? g_k : g_v);
            #pragma unroll
            for (int half = 0; half < 2; half++) {
                int row = bm + wm * 64 + i * 16 + g + half * 8;
                int b = row >> 11, n = row & (N_ - 1);
                float2 v = {acc[i][j][half * 2], acc[i][j][half * 2 + 1]};
                *(float2*)(dst + (((size_t)b * H_ + h) * N_ + n) * D_ + d) = v;
            }
        }
    }
}

// ---------------------------------------------------------------------------
// GEMM 2: out = g_att @ proj_w^T + proj_b
// ---------------------------------------------------------------------------
__global__ __launch_bounds__(128, 2) void proj_gemm(const float* __restrict__ W,
                                                    const float* __restrict__ bias,
                                                    float* __restrict__ out)
{
    extern __shared__ float sm[];
    int bm = blockIdx.y * 128, bn = blockIdx.x * 128;
    float acc[4][8][4];
    #pragma unroll
    for (int i = 0; i < 4; i++)
        #pragma unroll
        for (int j = 0; j < 8; j++)
            #pragma unroll
            for (int q = 0; q < 4; q++) acc[i][j][q] = 0.f;

    gemm128(g_att, W, bm, bn, acc, sm);

    int tid = threadIdx.x, wid = tid >> 5, lane = tid & 31;
    int wm = wid >> 1, wn = wid & 1;
    int g = lane >> 2, tg = lane & 3;

    #pragma unroll
    for (int i = 0; i < 4; i++) {
        #pragma unroll
        for (int j = 0; j < 8; j++) {
            int col = bn + wn * 64 + j * 8 + 2 * tg;
            float b0 = bias[col], b1 = bias[col + 1];
            #pragma unroll
            for (int half = 0; half < 2; half++) {
                int row = bm + wm * 64 + i * 16 + g + half * 8;
                float2 v = {acc[i][j][half * 2] + b0, acc[i][j][half * 2 + 1] + b1};
                *(float2*)(out + (size_t)row * C_ + col) = v;
            }
        }
    }
}

// ---------------------------------------------------------------------------
// Causal flash attention, tf32 MMA. Block = (qtile 128 rows, head, batch),
// 4 warps x 32 q-rows. V stored TRANSPOSED (Vt[d][key]) so PV B-fragments
// come from ldmatrix like QK^T. ex2.approx softmax. 2 CTAs/SM.
// ---------------------------------------------------------------------------
__device__ __forceinline__ unsigned aswz(int row, int col) {   // word idx
    return (unsigned)(row * 64 + ((((col >> 2) ^ (row & 7)) << 2) | (col & 3)));
}

#define QS_OFF 0
#define KS_OFF (128*64)
#define VS_OFF (KS_OFF + 64*64)
#define SS_OFF (VS_OFF + 64*64)
#define ATT_SMEM ((SS_OFF + 128*64) * 4)

__global__ __launch_bounds__(128, 2) void attn_kernel()
{
    extern __shared__ float sm[];
    unsigned sbase = (unsigned)__cvta_generic_to_shared(sm);

    int qt = (int)(gridDim.x - 1 - blockIdx.x);   // heavy tiles first
    int hh = blockIdx.y, b = blockIdx.z;
    int tid = threadIdx.x, w = tid >> 5, lane = tid & 31;
    int g = lane >> 2, tg = lane & 3;
    int wr = w * 32;

    int arow_l = (lane & 7) + (((lane >> 3) & 1) << 3);
    int acol_l = (lane >> 4) << 2;
    int brow_l = (lane & 7) + (((lane >> 4) & 1) << 3);
    int bcol_l = ((lane >> 3) & 1) << 2;

    const float* Qg = g_q + ((size_t)b * H_ + hh) * N_ * D_;
    const float* Kg = g_k + ((size_t)b * H_ + hh) * N_ * D_;
    const float* Vg = g_v + ((size_t)b * H_ + hh) * N_ * D_;

    const float SC2 = 0.125f * 1.44269504088896f;  // scale * log2(e)

    int lr = tid >> 4, lc4 = (tid & 15) * 4;       // K loader: +8 rows per t
    int vd = tid >> 1, vk0 = (tid & 1) * 4;        // Vt loader: d-row, key base

    // Load Q tile (scaled + tf32-rounded) — 128 rows x 64 cols
    #pragma unroll
    for (int t = 0; t < 16; t++) {
        int r = lr + t * 8;
        float4 v = *(const float4*)(Qg + (size_t)(qt * 128 + r) * D_ + lc4);
        uint4 u = {f2tf(v.x * SC2), f2tf(v.y * SC2), f2tf(v.z * SC2), f2tf(v.w * SC2)};
        *(uint4*)(sm + QS_OFF + aswz(r, lc4)) = u;
    }

    float o[2][8][4];
    #pragma unroll
    for (int i = 0; i < 2; i++)
        #pragma unroll
        for (int nt = 0; nt < 8; nt++)
            #pragma unroll
            for (int q = 0; q < 4; q++) o[i][nt][q] = 0.f;
    float mrow[2][2], lrow_[2][2];
    #pragma unroll
    for (int i = 0; i < 2; i++) { mrow[i][0] = mrow[i][1] = -1e30f; lrow_[i][0] = lrow_[i][1] = 0.f; }

    // Prefetch K tile 0 into registers
    float4 kreg[8];
    #pragma unroll
    for (int t = 0; t < 8; t++)
        kreg[t] = *(const float4*)(Kg + (size_t)(lr + t * 8) * D_ + lc4);

    int nkt = 2 * qt + 2;
    for (int kt = 0; kt < nkt; kt++) {
        __syncthreads();                 // prior tile's smem reads complete
        // STS K (cvt) from prefetched regs
        #pragma unroll
        for (int t = 0; t < 8; t++)
            *(uint4*)(sm + KS_OFF + aswz(lr + t * 8, lc4)) = cvt4(kreg[t]);
        // Issue transposed V loads for this tile (32 scalar LDG, d fixed per thread)
        float vr[8][4];
        #pragma unroll
        for (int t = 0; t < 8; t++)
            #pragma unroll
            for (int i2 = 0; i2 < 4; i2++)
                vr[t][i2] = Vg[(size_t)(kt * 64 + vk0 + 8 * t + i2) * D_ + vd];
        __syncthreads();                 // K visible

        bool active = !(kt * 64 > qt * 128 + wr + 31);

        if (active) {
            // S = Q K^T
            float s[2][8][4];
            #pragma unroll
            for (int i = 0; i < 2; i++)
                #pragma unroll
                for (int nt = 0; nt < 8; nt++)
                    #pragma unroll
                    for (int q = 0; q < 4; q++) s[i][nt][q] = 0.f;

            unsigned qbase = sbase + QS_OFF * 4u;
            unsigned kbase = sbase + KS_OFF * 4u;
            #pragma unroll
            for (int ks = 0; ks < 8; ks++) {
                int k0 = ks * 8;
                unsigned kf[4][4];
                #pragma unroll
                for (int jp = 0; jp < 4; jp++)
                    ldsm4(kf[jp], kbase + aswz(jp * 16 + brow_l, k0 + bcol_l) * 4u);
                #pragma unroll
                for (int i = 0; i < 2; i++) {
                    unsigned af[4];
                    ldsm4(af, qbase + aswz(wr + i * 16 + arow_l, k0 + acol_l) * 4u);
                    #pragma unroll
                    for (int jp = 0; jp < 4; jp++) {
                        mma8(s[i][2 * jp],     af, &kf[jp][0]);
                        mma8(s[i][2 * jp + 1], af, &kf[jp][2]);
                    }
                }
            }

            // causal mask (tiles straddling the diagonal)
            if (kt * 64 + 63 > qt * 128 + wr) {
                #pragma unroll
                for (int i = 0; i < 2; i++) {
                    int row0 = qt * 128 + wr + i * 16 + g;
                    #pragma unroll
                    for (int nt = 0; nt < 8; nt++) {
                        int c0 = kt * 64 + nt * 8 + 2 * tg;
                        if (c0 > row0)         s[i][nt][0] = -1e30f;
                        if (c0 + 1 > row0)     s[i][nt][1] = -1e30f;
                        if (c0 > row0 + 8)     s[i][nt][2] = -1e30f;
                        if (c0 + 1 > row0 + 8) s[i][nt][3] = -1e30f;
                    }
                }
            }

            // online softmax (exp2 domain, ex2.approx) + P store
            #pragma unroll
            for (int i = 0; i < 2; i++) {
                float mx0 = -1e30f, mx1 = -1e30f;
                #pragma unroll
                for (int nt = 0; nt < 8; nt++) {
                    mx0 = fmaxf(mx0, fmaxf(s[i][nt][0], s[i][nt][1]));
                    mx1 = fmaxf(mx1, fmaxf(s[i][nt][2], s[i][nt][3]));
                }
                mx0 = fmaxf(mx0, __shfl_xor_sync(0xffffffffu, mx0, 1));
                mx0 = fmaxf(mx0, __shfl_xor_sync(0xffffffffu, mx0, 2));
                mx1 = fmaxf(mx1, __shfl_xor_sync(0xffffffffu, mx1, 1));
                mx1 = fmaxf(mx1, __shfl_xor_sync(0xffffffffu, mx1, 2));

                float nm0 = fmaxf(mrow[i][0], mx0), nm1 = fmaxf(mrow[i][1], mx1);
                float a0 = ex2(mrow[i][0] - nm0), a1 = ex2(mrow[i][1] - nm1);
                mrow[i][0] = nm0; mrow[i][1] = nm1;

                int r0 = wr + i * 16 + g;
                float ls0 = 0.f, ls1 = 0.f;
                #pragma unroll
                for (int nt = 0; nt < 8; nt++) {
                    float p0 = ex2(s[i][nt][0] - nm0);
                    float p1 = ex2(s[i][nt][1] - nm0);
                    float p2 = ex2(s[i][nt][2] - nm1);
                    float p3 = ex2(s[i][nt][3] - nm1);
                    ls0 += p0 + p1; ls1 += p2 + p3;
                    int c0 = nt * 8 + 2 * tg;
                    float2 v0 = {__uint_as_float(f2tf(p0)), __uint_as_float(f2tf(p1))};
                    *(float2*)(sm + SS_OFF + aswz(r0, c0)) = v0;
                    float2 v1 = {__uint_as_float(f2tf(p2)), __uint_as_float(f2tf(p3))};
                    *(float2*)(sm + SS_OFF + aswz(r0 + 8, c0)) = v1;
                }
                ls0 += __shfl_xor_sync(0xffffffffu, ls0, 1);
                ls0 += __shfl_xor_sync(0xffffffffu, ls0, 2);
                ls1 += __shfl_xor_sync(0xffffffffu, ls1, 1);
                ls1 += __shfl_xor_sync(0xffffffffu, ls1, 2);
                lrow_[i][0] = lrow_[i][0] * a0 + ls0;
                lrow_[i][1] = lrow_[i][1] * a1 + ls1;

                #pragma unroll
                for (int nt = 0; nt < 8; nt++) {
                    o[i][nt][0] *= a0; o[i][nt][1] *= a0;
                    o[i][nt][2] *= a1; o[i][nt][3] *= a1;
                }
            }
            __syncwarp();
        }

        // STS Vt (cvt): thread owns d-row vd, keys vk0+8t..+3 -> STS.128,
        // conflict-free under aswz because lanes span distinct (d&7).
        #pragma unroll
        for (int t = 0; t < 8; t++) {
            uint4 u = {f2tf(vr[t][0]), f2tf(vr[t][1]), f2tf(vr[t][2]), f2tf(vr[t][3])};
            *(uint4*)(sm + VS_OFF + aswz(vd, vk0 + 8 * t)) = u;
        }

        // Prefetch K for next tile (clamped, dummy on last iter)
        int ktn = (kt + 1 < N_ / 64) ? kt + 1 : kt;
        #pragma unroll
        for (int t = 0; t < 8; t++)
            kreg[t] = *(const float4*)(Kg + (size_t)(ktn * 64 + lr + t * 8) * D_ + lc4);

        __syncthreads();                 // Vt (and P via syncwarp) visible

        if (active) {
            // O += P V  (P and Vt both via ldmatrix — same shape as QK^T)
            unsigned pbase = sbase + SS_OFF * 4u;
            unsigned vbase = sbase + VS_OFF * 4u;
            #pragma unroll
            for (int ks = 0; ks < 8; ks++) {
                int k0 = ks * 8;
                unsigned vf[4][4];
                #pragma unroll
                for (int jp = 0; jp < 4; jp++)
                    ldsm4(vf[jp], vbase + aswz(jp * 16 + brow_l, k0 + bcol_l) * 4u);
                #pragma unroll
                for (int i = 0; i < 2; i++) {
                    unsigned pf[4];
                    ldsm4(pf, pbase + aswz(wr + i * 16 + arow_l, k0 + acol_l) * 4u);
                    #pragma unroll
                    for (int jp = 0; jp < 4; jp++) {
                        mma8(o[i][2 * jp],     pf, &vf[jp][0]);
                        mma8(o[i][2 * jp + 1], pf, &vf[jp][2]);
                    }
                }
            }
        }
    }

    // epilogue: normalize + write [B,N,C]
    float* Og = g_att + (size_t)b * N_ * C_ + (size_t)hh * 64;
    #pragma unroll
    for (int i = 0; i < 2; i++) {
        #pragma unroll
        for (int half = 0; half < 2; half++) {
            float inv = 1.f / lrow_[i][half];
            int row = qt * 128 + wr + i * 16 + g + half * 8;
            #pragma unroll
            for (int nt = 0; nt < 8; nt++) {
                int d = nt * 8 + 2 * tg;
                float2 v = {o[i][nt][half * 2] * inv, o[i][nt][half * 2 + 1] * inv};
                *(float2*)(Og + (size_t)row * C_ + d) = v;
            }
        }
    }
}

// ---------------------------------------------------------------------------
extern "C" void kernel_launch(void* const* d_in, const int* in_sizes, int n_in,
                              void* d_out, int out_size)
{
    const float* x      = (const float*)d_in[0];
    const float* qkv_w  = (const float*)d_in[1];
    const float* proj_w = (const float*)d_in[2];
    const float* proj_b = (const float*)d_in[3];
    float* out = (float*)d_out;

    int gsmem = 4 * AW * (int)sizeof(float);   // 65536 B
    cudaFuncSetAttribute(qkv_gemm, cudaFuncAttributeMaxDynamicSharedMemorySize, gsmem);
    cudaFuncSetAttribute(proj_gemm, cudaFuncAttributeMaxDynamicSharedMemorySize, gsmem);
    cudaFuncSetAttribute(attn_kernel, cudaFuncAttributeMaxDynamicSharedMemorySize, ATT_SMEM);

    qkv_gemm<<<dim3(24, 64), 128, gsmem>>>(x, qkv_w);
    attn_kernel<<<dim3(N_ / 128, H_, B_), 128, ATT_SMEM>>>();
    proj_gemm<<<dim3(8, 64), 128, gsmem>>>(proj_w, proj_b, out);
}

// round 10
// speedup vs baseline: 6.6287x; 1.5035x over previous
#include <cuda_runtime.h>
#include <cuda_fp16.h>

#define B_ 4
#define N_ 2048
#define C_ 1024
#define H_ 16
#define D_ 64

// Scratch (device globals — no runtime allocation allowed)
__device__ float g_q[(size_t)B_*H_*N_*D_];
__device__ float g_k[(size_t)B_*H_*N_*D_];
__device__ float g_v[(size_t)B_*H_*N_*D_];
__device__ float g_att[(size_t)B_*N_*C_];

__device__ __forceinline__ float ex2(float x) {
    float y; asm("ex2.approx.ftz.f32 %0, %1;" : "=f"(y) : "f"(x)); return y;
}
__device__ __forceinline__ unsigned h2(float a, float b) {
    __half2 h = __floats2half2_rn(a, b);
    return *(unsigned*)&h;
}
__device__ __forceinline__ uint4 cvt8(float4 a, float4 b) {
    uint4 u; u.x = h2(a.x, a.y); u.y = h2(a.z, a.w);
    u.z = h2(b.x, b.y); u.w = h2(b.z, b.w); return u;
}
__device__ __forceinline__ void mma16(float* c, const unsigned* a, unsigned b0, unsigned b1) {
    asm volatile("mma.sync.aligned.m16n8k16.row.col.f32.f16.f16.f32 "
        "{%0,%1,%2,%3}, {%4,%5,%6,%7}, {%8,%9}, {%0,%1,%2,%3};"
        : "+f"(c[0]), "+f"(c[1]), "+f"(c[2]), "+f"(c[3])
        : "r"(a[0]), "r"(a[1]), "r"(a[2]), "r"(a[3]), "r"(b0), "r"(b1));
}
__device__ __forceinline__ void ldsm4(unsigned* r, unsigned addr) {
    asm volatile("ldmatrix.sync.aligned.m8n8.x4.shared.b16 {%0,%1,%2,%3}, [%4];"
        : "=r"(r[0]), "=r"(r[1]), "=r"(r[2]), "=r"(r[3]) : "r"(addr));
}

// Rows are 64 halves = 128 bytes = 8 chunks of 16B; XOR swizzle on chunks.
__device__ __forceinline__ unsigned hswz(int row, int chunk) {   // byte offset
    return (unsigned)(row * 128 + (((chunk ^ (row & 7)) << 4)));
}

// ---------------------------------------------------------------------------
// GEMM core: C_tile[128x128] = A[128xK] * W[128xK]^T, K=1024, fp16 MMA k16.
// 128 threads, 4 warps (2x2), warp tile 64x64. Stage = 64 K-elems (128B rows),
// double buffer, staged LDG/cvt/STS interleaved into the 4 k16-steps.
// ---------------------------------------------------------------------------
#define STGB 32768   // bytes per buffer (A 16KB + B 16KB)
#define NSTG 16      // 1024 / 64

#define KSTEPH(ks)                                                          \
    {                                                                       \
        unsigned af[4][4], bf[4][4];                                        \
        _Pragma("unroll")                                                   \
        for (int i = 0; i < 4; i++)                                         \
            ldsm4(af[i], abase + hswz(wm * 64 + i * 16 + mrow_l, 2 * (ks) + chk_l)); \
        _Pragma("unroll")                                                   \
        for (int j = 0; j < 4; j++)                                         \
            ldsm4(bf[j], bbase + hswz(wn * 64 + j * 16 + mrow_l, 2 * (ks) + chk_l)); \
        _Pragma("unroll")                                                   \
        for (int i = 0; i < 4; i++)                                         \
            _Pragma("unroll")                                               \
            for (int j = 0; j < 4; j++) {                                   \
                mma16(acc[i][2 * j],     af[i], bf[j][0], bf[j][2]);        \
                mma16(acc[i][2 * j + 1], af[i], bf[j][1], bf[j][3]);        \
            }                                                               \
    }

__device__ __forceinline__ void gemm128h(const float* __restrict__ A,
                                         const float* __restrict__ W,
                                         int bm, int bn,
                                         float acc[4][8][4], char* smb)
{
    int tid = threadIdx.x, wid = tid >> 5, lane = tid & 31;
    int wm = wid >> 1, wn = wid & 1;
    unsigned sb = (unsigned)__cvta_generic_to_shared(smb);

    int lrow = tid >> 3;            // 0..15, rows +16t
    int lch = tid & 7;              // chunk (8 halves = 8 floats)
    int mrow_l = (lane & 7) + (((lane >> 3) & 1) << 3);
    int chk_l = lane >> 4;

    const float* Ap = A + (size_t)(bm + lrow) * C_ + lch * 8;
    const float* Wp = W + (size_t)(bn + lrow) * C_ + lch * 8;

    float4 ra[8];
    // prologue: stage 0 -> buffer 0
    #pragma unroll
    for (int t = 0; t < 8; t++) {
        const float* p = Ap + (size_t)(16 * t) * C_;
        ra[t & 3] = *(const float4*)p;
        float4 q = *(const float4*)(p + 4);
        *(uint4*)(smb + hswz(lrow + 16 * t, lch)) = cvt8(ra[t & 3], q);
    }
    #pragma unroll
    for (int t = 0; t < 8; t++) {
        const float* p = Wp + (size_t)(16 * t) * C_;
        ra[t & 3] = *(const float4*)p;
        float4 q = *(const float4*)(p + 4);
        *(uint4*)(smb + 16384 + hswz(lrow + 16 * t, lch)) = cvt8(ra[t & 3], q);
    }
    __syncthreads();

    int buf = 0;
    for (int s = 0; s < NSTG; s++) {
        bool more = (s + 1 < NSTG);
        int kc = (s + 1) * 64;
        unsigned abase = sb + (unsigned)buf * STGB;
        unsigned bbase = abase + 16384u;
        char* dst = smb + (buf ^ 1) * STGB;

        if (more) {
            #pragma unroll
            for (int t = 0; t < 4; t++) {
                ra[2 * t]     = *(const float4*)(Ap + (size_t)(16 * t) * C_ + kc);
                ra[2 * t + 1] = *(const float4*)(Ap + (size_t)(16 * t) * C_ + kc + 4);
            }
        }
        KSTEPH(0)
        if (more) {
            #pragma unroll
            for (int t = 0; t < 4; t++)
                *(uint4*)(dst + hswz(lrow + 16 * t, lch)) = cvt8(ra[2 * t], ra[2 * t + 1]);
            #pragma unroll
            for (int t = 0; t < 4; t++) {
                ra[2 * t]     = *(const float4*)(Ap + (size_t)(16 * (t + 4)) * C_ + kc);
                ra[2 * t + 1] = *(const float4*)(Ap + (size_t)(16 * (t + 4)) * C_ + kc + 4);
            }
        }
        KSTEPH(1)
        if (more) {
            #pragma unroll
            for (int t = 0; t < 4; t++)
                *(uint4*)(dst + hswz(lrow + 16 * (t + 4), lch)) = cvt8(ra[2 * t], ra[2 * t + 1]);
            #pragma unroll
            for (int t = 0; t < 4; t++) {
                ra[2 * t]     = *(const float4*)(Wp + (size_t)(16 * t) * C_ + kc);
                ra[2 * t + 1] = *(const float4*)(Wp + (size_t)(16 * t) * C_ + kc + 4);
            }
        }
        KSTEPH(2)
        if (more) {
            #pragma unroll
            for (int t = 0; t < 4; t++)
                *(uint4*)(dst + 16384 + hswz(lrow + 16 * t, lch)) = cvt8(ra[2 * t], ra[2 * t + 1]);
            #pragma unroll
            for (int t = 0; t < 4; t++) {
                ra[2 * t]     = *(const float4*)(Wp + (size_t)(16 * (t + 4)) * C_ + kc);
                ra[2 * t + 1] = *(const float4*)(Wp + (size_t)(16 * (t + 4)) * C_ + kc + 4);
            }
        }
        KSTEPH(3)
        if (more) {
            #pragma unroll
            for (int t = 0; t < 4; t++)
                *(uint4*)(dst + 16384 + hswz(lrow + 16 * (t + 4), lch)) = cvt8(ra[2 * t], ra[2 * t + 1]);
        }
        __syncthreads();
        buf ^= 1;
    }
}

// ---------------------------------------------------------------------------
// GEMM 1: qkv = x @ qkv_w^T, scattered into Q/K/V [B,H,N,D]
// ---------------------------------------------------------------------------
__global__ __launch_bounds__(128, 2) void qkv_gemm(const float* __restrict__ A,
                                                   const float* __restrict__ W)
{
    extern __shared__ char smc[];
    int bm = blockIdx.y * 128, bn = blockIdx.x * 128;
    float acc[4][8][4];
    #pragma unroll
    for (int i = 0; i < 4; i++)
        #pragma unroll
        for (int j = 0; j < 8; j++)
            #pragma unroll
            for (int q = 0; q < 4; q++) acc[i][j][q] = 0.f;

    gemm128h(A, W, bm, bn, acc, smc);

    int tid = threadIdx.x, wid = tid >> 5, lane = tid & 31;
    int wm = wid >> 1, wn = wid & 1;
    int g = lane >> 2, tg = lane & 3;

    #pragma unroll
    for (int i = 0; i < 4; i++) {
        #pragma unroll
        for (int j = 0; j < 8; j++) {
            int col = bn + wn * 64 + j * 8 + 2 * tg;
            int three = col >> 10, rem = col & 1023;
            int h = rem >> 6, d = rem & 63;
            float* dst = (three == 0) ? g_q : (three == 1 ? g_k : g_v);
            #pragma unroll
            for (int half = 0; half < 2; half++) {
                int row = bm + wm * 64 + i * 16 + g + half * 8;
                int b = row >> 11, n = row & (N_ - 1);
                float2 v = {acc[i][j][half * 2], acc[i][j][half * 2 + 1]};
                *(float2*)(dst + (((size_t)b * H_ + h) * N_ + n) * D_ + d) = v;
            }
        }
    }
}

// ---------------------------------------------------------------------------
// GEMM 2: out = g_att @ proj_w^T + proj_b
// ---------------------------------------------------------------------------
__global__ __launch_bounds__(128, 2) void proj_gemm(const float* __restrict__ W,
                                                    const float* __restrict__ bias,
                                                    float* __restrict__ out)
{
    extern __shared__ char smc[];
    int bm = blockIdx.y * 128, bn = blockIdx.x * 128;
    float acc[4][8][4];
    #pragma unroll
    for (int i = 0; i < 4; i++)
        #pragma unroll
        for (int j = 0; j < 8; j++)
            #pragma unroll
            for (int q = 0; q < 4; q++) acc[i][j][q] = 0.f;

    gemm128h(g_att, W, bm, bn, acc, smc);

    int tid = threadIdx.x, wid = tid >> 5, lane = tid & 31;
    int wm = wid >> 1, wn = wid & 1;
    int g = lane >> 2, tg = lane & 3;

    #pragma unroll
    for (int i = 0; i < 4; i++) {
        #pragma unroll
        for (int j = 0; j < 8; j++) {
            int col = bn + wn * 64 + j * 8 + 2 * tg;
            float b0 = bias[col], b1 = bias[col + 1];
            #pragma unroll
            for (int half = 0; half < 2; half++) {
                int row = bm + wm * 64 + i * 16 + g + half * 8;
                float2 v = {acc[i][j][half * 2] + b0, acc[i][j][half * 2 + 1] + b1};
                *(float2*)(out + (size_t)row * C_ + col) = v;
            }
        }
    }
}

// ---------------------------------------------------------------------------
// Causal flash attention, fp16 MMA k16. Block = (qtile 128 rows, head, batch),
// 4 warps x 32 q-rows. Q/K/P/Vt all fp16 via ldmatrix. ex2 softmax in fp32.
// smem: Q 16KB | K 8KB | Vt 8KB | S 16KB = 48KB.
// ---------------------------------------------------------------------------
#define QSB 0
#define KSB 16384
#define VSB 24576
#define SSB 32768
#define ATT_SMEM 49152

__global__ __launch_bounds__(128, 2) void attn_kernel()
{
    extern __shared__ char smc[];
    unsigned sbase = (unsigned)__cvta_generic_to_shared(smc);

    int qt = (int)(gridDim.x - 1 - blockIdx.x);   // heavy tiles first
    int hh = blockIdx.y, b = blockIdx.z;
    int tid = threadIdx.x, w = tid >> 5, lane = tid & 31;
    int g = lane >> 2, tg = lane & 3;
    int wr = w * 32;

    int mrow_l = (lane & 7) + (((lane >> 3) & 1) << 3);
    int chk_l = lane >> 4;

    const float* Qg = g_q + ((size_t)b * H_ + hh) * N_ * D_;
    const float* Kg = g_k + ((size_t)b * H_ + hh) * N_ * D_;
    const float* Vg = g_v + ((size_t)b * H_ + hh) * N_ * D_;

    const float SC2 = 0.125f * 1.44269504088896f;  // scale * log2(e)

    int lrow = tid >> 3, lch = tid & 7;            // Q/K loader
    int vd = tid >> 1, vp = tid & 1;               // Vt loader: d-row, key half

    // Load Q tile (scaled, fp16) — 128 rows
    #pragma unroll
    for (int t = 0; t < 8; t++) {
        int r = lrow + 16 * t;
        const float* p = Qg + (size_t)(qt * 128 + r) * D_ + lch * 8;
        float4 a = *(const float4*)p, q = *(const float4*)(p + 4);
        a.x *= SC2; a.y *= SC2; a.z *= SC2; a.w *= SC2;
        q.x *= SC2; q.y *= SC2; q.z *= SC2; q.w *= SC2;
        *(uint4*)(smc + QSB + hswz(r, lch)) = cvt8(a, q);
    }

    float o[2][8][4];
    #pragma unroll
    for (int i = 0; i < 2; i++)
        #pragma unroll
        for (int nt = 0; nt < 8; nt++)
            #pragma unroll
            for (int q = 0; q < 4; q++) o[i][nt][q] = 0.f;
    float mrow[2][2], lrow_[2][2];
    #pragma unroll
    for (int i = 0; i < 2; i++) { mrow[i][0] = mrow[i][1] = -1e30f; lrow_[i][0] = lrow_[i][1] = 0.f; }

    // Prefetch K tile 0 into registers (64 rows)
    float4 kreg[8];
    #pragma unroll
    for (int t = 0; t < 4; t++) {
        const float* p = Kg + (size_t)(lrow + 16 * t) * D_ + lch * 8;
        kreg[2 * t] = *(const float4*)p;
        kreg[2 * t + 1] = *(const float4*)(p + 4);
    }

    int nkt = 2 * qt + 2;
    for (int kt = 0; kt < nkt; kt++) {
        __syncthreads();                 // prior tile's smem reads complete
        // STS K (cvt) from prefetched regs
        #pragma unroll
        for (int t = 0; t < 4; t++)
            *(uint4*)(smc + KSB + hswz(lrow + 16 * t, lch)) = cvt8(kreg[2 * t], kreg[2 * t + 1]);
        // Issue transposed V loads: 8 chunks x 4 keys -> ALL 64 keys covered
        float vr[8][4];
        #pragma unroll
        for (int t = 0; t < 8; t++)
            #pragma unroll
            for (int i2 = 0; i2 < 4; i2++)
                vr[t][i2] = Vg[(size_t)(kt * 64 + 8 * t + 4 * vp + i2) * D_ + vd];
        __syncthreads();                 // K visible

        bool active = !(kt * 64 > qt * 128 + wr + 31);

        if (active) {
            // S = Q K^T  (k16 steps)
            float s[2][8][4];
            #pragma unroll
            for (int i = 0; i < 2; i++)
                #pragma unroll
                for (int nt = 0; nt < 8; nt++)
                    #pragma unroll
                    for (int q = 0; q < 4; q++) s[i][nt][q] = 0.f;

            #pragma unroll
            for (int ks = 0; ks < 4; ks++) {
                unsigned kf[4][4];
                #pragma unroll
                for (int jp = 0; jp < 4; jp++)
                    ldsm4(kf[jp], sbase + KSB + hswz(jp * 16 + mrow_l, 2 * ks + chk_l));
                #pragma unroll
                for (int i = 0; i < 2; i++) {
                    unsigned qf[4];
                    ldsm4(qf, sbase + QSB + hswz(wr + i * 16 + mrow_l, 2 * ks + chk_l));
                    #pragma unroll
                    for (int jp = 0; jp < 4; jp++) {
                        mma16(s[i][2 * jp],     qf, kf[jp][0], kf[jp][2]);
                        mma16(s[i][2 * jp + 1], qf, kf[jp][1], kf[jp][3]);
                    }
                }
            }

            // causal mask (tiles straddling the diagonal)
            if (kt * 64 + 63 > qt * 128 + wr) {
                #pragma unroll
                for (int i = 0; i < 2; i++) {
                    int row0 = qt * 128 + wr + i * 16 + g;
                    #pragma unroll
                    for (int nt = 0; nt < 8; nt++) {
                        int c0 = kt * 64 + nt * 8 + 2 * tg;
                        if (c0 > row0)         s[i][nt][0] = -1e30f;
                        if (c0 + 1 > row0)     s[i][nt][1] = -1e30f;
                        if (c0 > row0 + 8)     s[i][nt][2] = -1e30f;
                        if (c0 + 1 > row0 + 8) s[i][nt][3] = -1e30f;
                    }
                }
            }

            // online softmax (exp2 domain) + P store (fp16)
            #pragma unroll
            for (int i = 0; i < 2; i++) {
                float mx0 = -1e30f, mx1 = -1e30f;
                #pragma unroll
                for (int nt = 0; nt < 8; nt++) {
                    mx0 = fmaxf(mx0, fmaxf(s[i][nt][0], s[i][nt][1]));
                    mx1 = fmaxf(mx1, fmaxf(s[i][nt][2], s[i][nt][3]));
                }
                mx0 = fmaxf(mx0, __shfl_xor_sync(0xffffffffu, mx0, 1));
                mx0 = fmaxf(mx0, __shfl_xor_sync(0xffffffffu, mx0, 2));
                mx1 = fmaxf(mx1, __shfl_xor_sync(0xffffffffu, mx1, 1));
                mx1 = fmaxf(mx1, __shfl_xor_sync(0xffffffffu, mx1, 2));

                float nm0 = fmaxf(mrow[i][0], mx0), nm1 = fmaxf(mrow[i][1], mx1);
                float a0 = ex2(mrow[i][0] - nm0), a1 = ex2(mrow[i][1] - nm1);
                mrow[i][0] = nm0; mrow[i][1] = nm1;

                int r0 = wr + i * 16 + g;
                float ls0 = 0.f, ls1 = 0.f;
                #pragma unroll
                for (int nt = 0; nt < 8; nt++) {
                    float p0 = ex2(s[i][nt][0] - nm0);
                    float p1 = ex2(s[i][nt][1] - nm0);
                    float p2 = ex2(s[i][nt][2] - nm1);
                    float p3 = ex2(s[i][nt][3] - nm1);
                    ls0 += p0 + p1; ls1 += p2 + p3;
                    *(unsigned*)(smc + SSB + r0 * 128 + (((nt ^ (r0 & 7)) << 4) + 4 * tg)) = h2(p0, p1);
                    int r1 = r0 + 8;
                    *(unsigned*)(smc + SSB + r1 * 128 + (((nt ^ (r1 & 7)) << 4) + 4 * tg)) = h2(p2, p3);
                }
                ls0 += __shfl_xor_sync(0xffffffffu, ls0, 1);
                ls0 += __shfl_xor_sync(0xffffffffu, ls0, 2);
                ls1 += __shfl_xor_sync(0xffffffffu, ls1, 1);
                ls1 += __shfl_xor_sync(0xffffffffu, ls1, 2);
                lrow_[i][0] = lrow_[i][0] * a0 + ls0;
                lrow_[i][1] = lrow_[i][1] * a1 + ls1;

                #pragma unroll
                for (int nt = 0; nt < 8; nt++) {
                    o[i][nt][0] *= a0; o[i][nt][1] *= a0;
                    o[i][nt][2] *= a1; o[i][nt][3] *= a1;
                }
            }
            __syncwarp();
        }

        // STS Vt (fp16): thread owns d-row vd, chunk t keys 8t+4vp..+3
        #pragma unroll
        for (int t = 0; t < 8; t++) {
            uint2 u = {h2(vr[t][0], vr[t][1]), h2(vr[t][2], vr[t][3])};
            *(uint2*)(smc + VSB + vd * 128 + (((t ^ (vd & 7)) << 4) + vp * 8)) = u;
        }

        // Prefetch K for next tile (clamped, dummy on last iter)
        int ktn = (kt + 1 < N_ / 64) ? kt + 1 : kt;
        #pragma unroll
        for (int t = 0; t < 4; t++) {
            const float* p = Kg + (size_t)(ktn * 64 + lrow + 16 * t) * D_ + lch * 8;
            kreg[2 * t] = *(const float4*)p;
            kreg[2 * t + 1] = *(const float4*)(p + 4);
        }

        __syncthreads();                 // Vt (and P via syncwarp) visible

        if (active) {
            // O += P V  (P and Vt both via ldmatrix, k16 steps)
            #pragma unroll
            for (int ks = 0; ks < 4; ks++) {
                unsigned vf[4][4];
                #pragma unroll
                for (int jp = 0; jp < 4; jp++)
                    ldsm4(vf[jp], sbase + VSB + hswz(jp * 16 + mrow_l, 2 * ks + chk_l));
                #pragma unroll
                for (int i = 0; i < 2; i++) {
                    unsigned pf[4];
                    ldsm4(pf, sbase + SSB + hswz(wr + i * 16 + mrow_l, 2 * ks + chk_l));
                    #pragma unroll
                    for (int jp = 0; jp < 4; jp++) {
                        mma16(o[i][2 * jp],     pf, vf[jp][0], vf[jp][2]);
                        mma16(o[i][2 * jp + 1], pf, vf[jp][1], vf[jp][3]);
                    }
                }
            }
        }
    }

    // epilogue: normalize + write [B,N,C]
    float* Og = g_att + (size_t)b * N_ * C_ + (size_t)hh * 64;
    #pragma unroll
    for (int i = 0; i < 2; i++) {
        #pragma unroll
        for (int half = 0; half < 2; half++) {
            float inv = 1.f / lrow_[i][half];
            int row = qt * 128 + wr + i * 16 + g + half * 8;
            #pragma unroll
            for (int nt = 0; nt < 8; nt++) {
                int d = nt * 8 + 2 * tg;
                float2 v = {o[i][nt][half * 2] * inv, o[i][nt][half * 2 + 1] * inv};
                *(float2*)(Og + (size_t)row * C_ + d) = v;
            }
        }
    }
}

// ---------------------------------------------------------------------------
extern "C" void kernel_launch(void* const* d_in, const int* in_sizes, int n_in,
                              void* d_out, int out_size)
{
    const float* x      = (const float*)d_in[0];
    const float* qkv_w  = (const float*)d_in[1];
    const float* proj_w = (const float*)d_in[2];
    const float* proj_b = (const float*)d_in[3];
    float* out = (float*)d_out;

    int gsmem = 2 * STGB;   // 65536 B
    cudaFuncSetAttribute(qkv_gemm, cudaFuncAttributeMaxDynamicSharedMemorySize, gsmem);
    cudaFuncSetAttribute(proj_gemm, cudaFuncAttributeMaxDynamicSharedMemorySize, gsmem);
    cudaFuncSetAttribute(attn_kernel, cudaFuncAttributeMaxDynamicSharedMemorySize, ATT_SMEM);

    qkv_gemm<<<dim3(24, 64), 128, gsmem>>>(x, qkv_w);
    attn_kernel<<<dim3(N_ / 128, H_, B_), 128, ATT_SMEM>>>();
    proj_gemm<<<dim3(8, 64), 128, gsmem>>>(proj_w, proj_b, out);
}

// round 14
// speedup vs baseline: 8.4949x; 1.2815x over previous
#include <cuda_runtime.h>
#include <cuda_fp16.h>

#define B_ 4
#define N_ 2048
#define C_ 1024
#define H_ 16
#define D_ 64
#define M_ (B_*N_)

// Scratch (device globals — no runtime allocation allowed)
__device__ __half xh_g[(size_t)M_*C_];
__device__ __half qwh_g[(size_t)3*C_*C_];
__device__ __half pwh_g[(size_t)C_*C_];
__device__ __half qh_g[(size_t)B_*H_*N_*D_];
__device__ __half kh_g[(size_t)B_*H_*N_*D_];
__device__ __half vh_g[(size_t)B_*H_*N_*D_];
__device__ __half atth_g[(size_t)B_*N_*C_];

__device__ __forceinline__ float ex2(float x) {
    float y; asm("ex2.approx.ftz.f32 %0, %1;" : "=f"(y) : "f"(x)); return y;
}
__device__ __forceinline__ unsigned h2(float a, float b) {
    __half2 h = __floats2half2_rn(a, b);
    return *(unsigned*)&h;
}
__device__ __forceinline__ uint4 cvt8(float4 a, float4 b) {
    uint4 u; u.x = h2(a.x, a.y); u.y = h2(a.z, a.w);
    u.z = h2(b.x, b.y); u.w = h2(b.z, b.w); return u;
}
__device__ __forceinline__ void mma16(float* c, const unsigned* a, unsigned b0, unsigned b1) {
    asm volatile("mma.sync.aligned.m16n8k16.row.col.f32.f16.f16.f32 "
        "{%0,%1,%2,%3}, {%4,%5,%6,%7}, {%8,%9}, {%0,%1,%2,%3};"
        : "+f"(c[0]), "+f"(c[1]), "+f"(c[2]), "+f"(c[3])
        : "r"(a[0]), "r"(a[1]), "r"(a[2]), "r"(a[3]), "r"(b0), "r"(b1));
}
__device__ __forceinline__ void ldsm4(unsigned* r, unsigned addr) {
    asm volatile("ldmatrix.sync.aligned.m8n8.x4.shared.b16 {%0,%1,%2,%3}, [%4];"
        : "=r"(r[0]), "=r"(r[1]), "=r"(r[2]), "=r"(r[3]) : "r"(addr));
}
__device__ __forceinline__ void ldsm4t(unsigned* r, unsigned addr) {
    asm volatile("ldmatrix.sync.aligned.m8n8.x4.trans.shared.b16 {%0,%1,%2,%3}, [%4];"
        : "=r"(r[0]), "=r"(r[1]), "=r"(r[2]), "=r"(r[3]) : "r"(addr));
}
__device__ __forceinline__ void cp16(unsigned dst, const void* src) {
    asm volatile("cp.async.cg.shared.global [%0], [%1], 16;" :: "r"(dst), "l"(src));
}
__device__ __forceinline__ void cp_commit() {
    asm volatile("cp.async.commit_group;" ::: "memory");
}

// Rows are 64 halves = 128 bytes = 8 chunks of 16B; XOR swizzle on chunks.
__device__ __forceinline__ unsigned hswz(int row, int chunk) {   // byte offset
    return (unsigned)(row * 128 + (((chunk ^ (row & 7)) << 4)));
}

// ---------------------------------------------------------------------------
// fp32 -> fp16 pre-conversion (x, qkv_w, proj_w)
// ---------------------------------------------------------------------------
__global__ __launch_bounds__(256) void cvt_kernel(const float* __restrict__ src,
                                                  int sel, int n)
{
    __half* dst = (sel == 0) ? xh_g : (sel == 1) ? qwh_g : pwh_g;
    int i = (blockIdx.x * 256 + threadIdx.x) * 8;
    if (i < n) {
        float4 a = *(const float4*)(src + i);
        float4 b = *(const float4*)(src + i + 4);
        *(uint4*)(dst + i) = cvt8(a, b);
    }
}

// ---------------------------------------------------------------------------
// GEMM core: C_tile[128x128] = A[128xK] * W[128xK]^T, K=1024, fp16 in gmem.
// 128 threads, 4 warps (2x2), warp tile 64x64. Stage = 64 K-halves (128B rows),
// cp.async 3-stage ring, 1 barrier per stage.
// ---------------------------------------------------------------------------
#define STGB 32768   // bytes per stage (A 16KB + B 16KB)
#define NSTG 16      // 1024 / 64
#define GEMM_SMEM (3*STGB)

__device__ __forceinline__ void g_issue(unsigned sb, unsigned ring,
                                        const __half* Ap, const __half* Wp,
                                        int kc, int lrow, int lch)
{
    #pragma unroll
    for (int t = 0; t < 8; t++)
        cp16(sb + ring + hswz(lrow + 16 * t, lch), Ap + (size_t)(16 * t) * C_ + kc);
    #pragma unroll
    for (int t = 0; t < 8; t++)
        cp16(sb + ring + 16384u + hswz(lrow + 16 * t, lch), Wp + (size_t)(16 * t) * C_ + kc);
}

#define KSTEPH(ks)                                                          \
    {                                                                       \
        unsigned af[4][4], bf[4][4];                                        \
        _Pragma("unroll")                                                   \
        for (int i = 0; i < 4; i++)                                         \
            ldsm4(af[i], abase + hswz(wm * 64 + i * 16 + mrow_l, 2 * (ks) + chk_l)); \
        _Pragma("unroll")                                                   \
        for (int j = 0; j < 4; j++)                                         \
            ldsm4(bf[j], bbase + hswz(wn * 64 + j * 16 + mrow_l, 2 * (ks) + chk_l)); \
        _Pragma("unroll")                                                   \
        for (int i = 0; i < 4; i++)                                         \
            _Pragma("unroll")                                               \
            for (int j = 0; j < 4; j++) {                                   \
                mma16(acc[i][2 * j],     af[i], bf[j][0], bf[j][2]);        \
                mma16(acc[i][2 * j + 1], af[i], bf[j][1], bf[j][3]);        \
            }                                                               \
    }

__device__ __forceinline__ void gemm_h(const __half* __restrict__ A,
                                       const __half* __restrict__ W,
                                       int bm, int bn,
                                       float acc[4][8][4], char* smb)
{
    int tid = threadIdx.x, wid = tid >> 5, lane = tid & 31;
    int wm = wid >> 1, wn = wid & 1;
    unsigned sb = (unsigned)__cvta_generic_to_shared(smb);

    int lrow = tid >> 3;            // 0..15, rows +16t
    int lch = tid & 7;              // 16B chunk
    int mrow_l = (lane & 7) + (((lane >> 3) & 1) << 3);
    int chk_l = lane >> 4;

    const __half* Ap = A + (size_t)(bm + lrow) * C_ + lch * 8;
    const __half* Wp = W + (size_t)(bn + lrow) * C_ + lch * 8;

    g_issue(sb, 0, Ap, Wp, 0, lrow, lch);  cp_commit();
    g_issue(sb, STGB, Ap, Wp, 64, lrow, lch);  cp_commit();

    for (int s = 0; s < NSTG; s++) {
        if (s < NSTG - 1) asm volatile("cp.async.wait_group 1;" ::: "memory");
        else              asm volatile("cp.async.wait_group 0;" ::: "memory");
        __syncthreads();
        if (s + 2 < NSTG) {
            g_issue(sb, (unsigned)((s + 2) % 3) * STGB, Ap, Wp, (s + 2) * 64, lrow, lch);
            cp_commit();
        }
        unsigned abase = sb + (unsigned)(s % 3) * STGB;
        unsigned bbase = abase + 16384u;
        KSTEPH(0)
        KSTEPH(1)
        KSTEPH(2)
        KSTEPH(3)
    }
    __syncthreads();
}

// ---------------------------------------------------------------------------
// GEMM 1: qkv = x @ qkv_w^T -> fp16 q(scaled)/k/v [B,H,N,D]
// ---------------------------------------------------------------------------
#define SC2F 0.18033688f   // 0.125 * log2(e)

__global__ __launch_bounds__(128, 2) void qkv_gemm()
{
    extern __shared__ char smc[];
    int bm = blockIdx.y * 128, bn = blockIdx.x * 128;
    float acc[4][8][4];
    #pragma unroll
    for (int i = 0; i < 4; i++)
        #pragma unroll
        for (int j = 0; j < 8; j++)
            #pragma unroll
            for (int q = 0; q < 4; q++) acc[i][j][q] = 0.f;

    gemm_h(xh_g, qwh_g, bm, bn, acc, smc);

    int tid = threadIdx.x, wid = tid >> 5, lane = tid & 31;
    int wm = wid >> 1, wn = wid & 1;
    int g = lane >> 2, tg = lane & 3;

    #pragma unroll
    for (int i = 0; i < 4; i++) {
        #pragma unroll
        for (int j = 0; j < 8; j++) {
            int col = bn + wn * 64 + j * 8 + 2 * tg;
            int three = col >> 10, rem = col & 1023;
            int h = rem >> 6, d = rem & 63;
            __half* dst = (three == 0) ? qh_g : (three == 1 ? kh_g : vh_g);
            float sc = (three == 0) ? SC2F : 1.0f;
            #pragma unroll
            for (int half = 0; half < 2; half++) {
                int row = bm + wm * 64 + i * 16 + g + half * 8;
                int b = row >> 11, n = row & (N_ - 1);
                *(unsigned*)(dst + (((size_t)b * H_ + h) * N_ + n) * D_ + d) =
                    h2(acc[i][j][half * 2] * sc, acc[i][j][half * 2 + 1] * sc);
            }
        }
    }
}

// ---------------------------------------------------------------------------
// GEMM 2: out = atth @ proj_w^T + proj_b  (fp32 out)
// ---------------------------------------------------------------------------
__global__ __launch_bounds__(128, 2) void proj_gemm(const float* __restrict__ bias,
                                                    float* __restrict__ out)
{
    extern __shared__ char smc[];
    int bm = blockIdx.y * 128, bn = blockIdx.x * 128;
    float acc[4][8][4];
    #pragma unroll
    for (int i = 0; i < 4; i++)
        #pragma unroll
        for (int j = 0; j < 8; j++)
            #pragma unroll
            for (int q = 0; q < 4; q++) acc[i][j][q] = 0.f;

    gemm_h(atth_g, pwh_g, bm, bn, acc, smc);

    int tid = threadIdx.x, wid = tid >> 5, lane = tid & 31;
    int wm = wid >> 1, wn = wid & 1;
    int g = lane >> 2, tg = lane & 3;

    #pragma unroll
    for (int i = 0; i < 4; i++) {
        #pragma unroll
        for (int j = 0; j < 8; j++) {
            int col = bn + wn * 64 + j * 8 + 2 * tg;
            float b0 = bias[col], b1 = bias[col + 1];
            #pragma unroll
            for (int half = 0; half < 2; half++) {
                int row = bm + wm * 64 + i * 16 + g + half * 8;
                float2 v = {acc[i][j][half * 2] + b0, acc[i][j][half * 2 + 1] + b1};
                *(float2*)(out + (size_t)row * C_ + col) = v;
            }
        }
    }
}

// ---------------------------------------------------------------------------
// Causal flash attention, fp16 in gmem. Block = (qtile 128, head, batch),
// 4 warps x 32 q-rows. cp.async Q + double-buffered K/V tiles;
// V fed to PV via ldmatrix.trans (row-major [key][d], no transpose pass).
// smem layout (FIXED): Q [0,16K) | slot0 [16K,32K) | slot1 [32K,48K) | S [48K,64K)
// ---------------------------------------------------------------------------
#define QSB 0
#define RK(r) (16384u + (unsigned)(r) * 16384u)
#define RV(r) (RK(r) + 8192u)
#define SSB 49152u
#define ATT_SMEM 65536

__device__ __forceinline__ void kv_issue(unsigned sb, int ring, int kt,
                                         const __half* Kg, const __half* Vg,
                                         int krow, int kch)
{
    #pragma unroll
    for (int t = 0; t < 2; t++) {
        int row = krow + 32 * t;
        #pragma unroll
        for (int cc = 0; cc < 2; cc++) {
            int ch = kch + 4 * cc;
            const __half* ks = Kg + (size_t)(kt * 64 + row) * D_ + ch * 8;
            const __half* vs = Vg + (size_t)(kt * 64 + row) * D_ + ch * 8;
            cp16(sb + RK(ring) + hswz(row, ch), ks);
            cp16(sb + RV(ring) + hswz(row, ch), vs);
        }
    }
}

__global__ __launch_bounds__(128, 2) void attn_kernel()
{
    extern __shared__ char smc[];
    unsigned sb = (unsigned)__cvta_generic_to_shared(smc);

    int qt = (int)(gridDim.x - 1 - blockIdx.x);   // heavy tiles first
    int hh = blockIdx.y, b = blockIdx.z;
    int tid = threadIdx.x, w = tid >> 5, lane = tid & 31;
    int g = lane >> 2, tg = lane & 3;
    int wr = w * 32;

    int mrow_l = (lane & 7) + (((lane >> 3) & 1) << 3);
    int chk_l = lane >> 4;

    const __half* Qg = qh_g + ((size_t)b * H_ + hh) * N_ * D_;
    const __half* Kg = kh_g + ((size_t)b * H_ + hh) * N_ * D_;
    const __half* Vg = vh_g + ((size_t)b * H_ + hh) * N_ * D_;

    int lrow = tid >> 3, lch = tid & 7;            // Q loader
    int krow = tid >> 2, kch = tid & 3;            // K/V loader

    // prologue: Q tile + KV tile 0 in one group
    #pragma unroll
    for (int t = 0; t < 8; t++)
        cp16(sb + QSB + hswz(lrow + 16 * t, lch),
             Qg + (size_t)(qt * 128 + lrow + 16 * t) * D_ + lch * 8);
    kv_issue(sb, 0, 0, Kg, Vg, krow, kch);
    cp_commit();

    float o[2][8][4];
    #pragma unroll
    for (int i = 0; i < 2; i++)
        #pragma unroll
        for (int nt = 0; nt < 8; nt++)
            #pragma unroll
            for (int q = 0; q < 4; q++) o[i][nt][q] = 0.f;
    float mrow[2][2], lrow_[2][2];
    #pragma unroll
    for (int i = 0; i < 2; i++) { mrow[i][0] = mrow[i][1] = -1e30f; lrow_[i][0] = lrow_[i][1] = 0.f; }

    int nkt = 2 * qt + 2;
    for (int kt = 0; kt < nkt; kt++) {
        __syncthreads();                 // prior tile's ring reads complete
        if (kt + 1 < nkt) {
            kv_issue(sb, (kt + 1) & 1, kt + 1, Kg, Vg, krow, kch);
            cp_commit();
            asm volatile("cp.async.wait_group 1;" ::: "memory");
        } else {
            asm volatile("cp.async.wait_group 0;" ::: "memory");
        }
        __syncthreads();                 // stage kt visible

        bool active = !(kt * 64 > qt * 128 + wr + 31);
        unsigned kbase = sb + RK(kt & 1);
        unsigned vbase = sb + RV(kt & 1);

        if (active) {
            // S = Q K^T  (k16 steps)
            float s[2][8][4];
            #pragma unroll
            for (int i = 0; i < 2; i++)
                #pragma unroll
                for (int nt = 0; nt < 8; nt++)
                    #pragma unroll
                    for (int q = 0; q < 4; q++) s[i][nt][q] = 0.f;

            #pragma unroll
            for (int ks = 0; ks < 4; ks++) {
                unsigned kf[4][4];
                #pragma unroll
                for (int jp = 0; jp < 4; jp++)
                    ldsm4(kf[jp], kbase + hswz(jp * 16 + mrow_l, 2 * ks + chk_l));
                #pragma unroll
                for (int i = 0; i < 2; i++) {
                    unsigned qf[4];
                    ldsm4(qf, sb + QSB + hswz(wr + i * 16 + mrow_l, 2 * ks + chk_l));
                    #pragma unroll
                    for (int jp = 0; jp < 4; jp++) {
                        mma16(s[i][2 * jp],     qf, kf[jp][0], kf[jp][2]);
                        mma16(s[i][2 * jp + 1], qf, kf[jp][1], kf[jp][3]);
                    }
                }
            }

            // causal mask (tiles straddling the diagonal)
            if (kt * 64 + 63 > qt * 128 + wr) {
                #pragma unroll
                for (int i = 0; i < 2; i++) {
                    int row0 = qt * 128 + wr + i * 16 + g;
                    #pragma unroll
                    for (int nt = 0; nt < 8; nt++) {
                        int c0 = kt * 64 + nt * 8 + 2 * tg;
                        if (c0 > row0)         s[i][nt][0] = -1e30f;
                        if (c0 + 1 > row0)     s[i][nt][1] = -1e30f;
                        if (c0 > row0 + 8)     s[i][nt][2] = -1e30f;
                        if (c0 + 1 > row0 + 8) s[i][nt][3] = -1e30f;
                    }
                }
            }

            // online softmax (exp2 domain) + P store (fp16)
            #pragma unroll
            for (int i = 0; i < 2; i++) {
                float mx0 = -1e30f, mx1 = -1e30f;
                #pragma unroll
                for (int nt = 0; nt < 8; nt++) {
                    mx0 = fmaxf(mx0, fmaxf(s[i][nt][0], s[i][nt][1]));
                    mx1 = fmaxf(mx1, fmaxf(s[i][nt][2], s[i][nt][3]));
                }
                mx0 = fmaxf(mx0, __shfl_xor_sync(0xffffffffu, mx0, 1));
                mx0 = fmaxf(mx0, __shfl_xor_sync(0xffffffffu, mx0, 2));
                mx1 = fmaxf(mx1, __shfl_xor_sync(0xffffffffu, mx1, 1));
                mx1 = fmaxf(mx1, __shfl_xor_sync(0xffffffffu, mx1, 2));

                float nm0 = fmaxf(mrow[i][0], mx0), nm1 = fmaxf(mrow[i][1], mx1);
                float a0 = ex2(mrow[i][0] - nm0), a1 = ex2(mrow[i][1] - nm1);
                mrow[i][0] = nm0; mrow[i][1] = nm1;

                int r0 = wr + i * 16 + g;
                float ls0 = 0.f, ls1 = 0.f;
                #pragma unroll
                for (int nt = 0; nt < 8; nt++) {
                    float p0 = ex2(s[i][nt][0] - nm0);
                    float p1 = ex2(s[i][nt][1] - nm0);
                    float p2 = ex2(s[i][nt][2] - nm1);
                    float p3 = ex2(s[i][nt][3] - nm1);
                    ls0 += p0 + p1; ls1 += p2 + p3;
                    *(unsigned*)(smc + SSB + r0 * 128 + (((nt ^ (r0 & 7)) << 4) + 4 * tg)) = h2(p0, p1);
                    int r1 = r0 + 8;
                    *(unsigned*)(smc + SSB + r1 * 128 + (((nt ^ (r1 & 7)) << 4) + 4 * tg)) = h2(p2, p3);
                }
                ls0 += __shfl_xor_sync(0xffffffffu, ls0, 1);
                ls0 += __shfl_xor_sync(0xffffffffu, ls0, 2);
                ls1 += __shfl_xor_sync(0xffffffffu, ls1, 1);
                ls1 += __shfl_xor_sync(0xffffffffu, ls1, 2);
                lrow_[i][0] = lrow_[i][0] * a0 + ls0;
                lrow_[i][1] = lrow_[i][1] * a1 + ls1;

                #pragma unroll
                for (int nt = 0; nt < 8; nt++) {
                    o[i][nt][0] *= a0; o[i][nt][1] *= a0;
                    o[i][nt][2] *= a1; o[i][nt][3] *= a1;
                }
            }
            __syncwarp();

            // O += P V  (P non-trans, V via ldmatrix.trans on [key][d])
            #pragma unroll
            for (int ks = 0; ks < 4; ks++) {
                unsigned vf[4][4];
                #pragma unroll
                for (int nt2 = 0; nt2 < 4; nt2++)
                    ldsm4t(vf[nt2], vbase + hswz(16 * ks + mrow_l, 2 * nt2 + chk_l));
                #pragma unroll
                for (int i = 0; i < 2; i++) {
                    unsigned pf[4];
                    ldsm4(pf, sb + SSB + hswz(wr + i * 16 + mrow_l, 2 * ks + chk_l));
                    #pragma unroll
                    for (int nt2 = 0; nt2 < 4; nt2++) {
                        mma16(o[i][2 * nt2],     pf, vf[nt2][0], vf[nt2][1]);
                        mma16(o[i][2 * nt2 + 1], pf, vf[nt2][2], vf[nt2][3]);
                    }
                }
            }
        }
    }

    // epilogue: normalize + write fp16 [B,N,C]
    __half* Og = atth_g + (size_t)b * N_ * C_ + (size_t)hh * 64;
    #pragma unroll
    for (int i = 0; i < 2; i++) {
        #pragma unroll
        for (int half = 0; half < 2; half++) {
            float inv = 1.f / lrow_[i][half];
            int row = qt * 128 + wr + i * 16 + g + half * 8;
            #pragma unroll
            for (int nt = 0; nt < 8; nt++) {
                int d = nt * 8 + 2 * tg;
                *(unsigned*)(Og + (size_t)row * C_ + d) =
                    h2(o[i][nt][half * 2] * inv, o[i][nt][half * 2 + 1] * inv);
            }
        }
    }
}

// ---------------------------------------------------------------------------
extern "C" void kernel_launch(void* const* d_in, const int* in_sizes, int n_in,
                              void* d_out, int out_size)
{
    const float* x      = (const float*)d_in[0];
    const float* qkv_w  = (const float*)d_in[1];
    const float* proj_w = (const float*)d_in[2];
    const float* proj_b = (const float*)d_in[3];
    float* out = (float*)d_out;

    cudaFuncSetAttribute(qkv_gemm, cudaFuncAttributeMaxDynamicSharedMemorySize, GEMM_SMEM);
    cudaFuncSetAttribute(proj_gemm, cudaFuncAttributeMaxDynamicSharedMemorySize, GEMM_SMEM);
    cudaFuncSetAttribute(attn_kernel, cudaFuncAttributeMaxDynamicSharedMemorySize, ATT_SMEM);

    cvt_kernel<<<(M_ * C_) / (256 * 8), 256>>>(x, 0, M_ * C_);
    cvt_kernel<<<(3 * C_ * C_) / (256 * 8), 256>>>(qkv_w, 1, 3 * C_ * C_);
    cvt_kernel<<<(C_ * C_) / (256 * 8), 256>>>(proj_w, 2, C_ * C_);

    qkv_gemm<<<dim3(24, 64), 128, GEMM_SMEM>>>();
    attn_kernel<<<dim3(N_ / 128, H_, B_), 128, ATT_SMEM>>>();
    proj_gemm<<<dim3(8, 64), 128, GEMM_SMEM>>>(proj_b, out);
}

// round 15
// speedup vs baseline: 9.0413x; 1.0643x over previous
#include <cuda_runtime.h>
#include <cuda_fp16.h>

#define B_ 4
#define N_ 2048
#define C_ 1024
#define H_ 16
#define D_ 64
#define M_ (B_*N_)

// Scratch (device globals — no runtime allocation allowed)
__device__ __half xh_g[(size_t)M_*C_];
__device__ __half qwh_g[(size_t)3*C_*C_];
__device__ __half pwh_g[(size_t)C_*C_];
__device__ __half qh_g[(size_t)B_*H_*N_*D_];
__device__ __half kh_g[(size_t)B_*H_*N_*D_];
__device__ __half vh_g[(size_t)B_*H_*N_*D_];
__device__ __half atth_g[(size_t)B_*N_*C_];

__device__ __forceinline__ float ex2(float x) {
    float y; asm("ex2.approx.ftz.f32 %0, %1;" : "=f"(y) : "f"(x)); return y;
}
__device__ __forceinline__ unsigned h2(float a, float b) {
    __half2 h = __floats2half2_rn(a, b);
    return *(unsigned*)&h;
}
__device__ __forceinline__ uint4 cvt8(float4 a, float4 b) {
    uint4 u; u.x = h2(a.x, a.y); u.y = h2(a.z, a.w);
    u.z = h2(b.x, b.y); u.w = h2(b.z, b.w); return u;
}
__device__ __forceinline__ void mma16(float* c, const unsigned* a, unsigned b0, unsigned b1) {
    asm volatile("mma.sync.aligned.m16n8k16.row.col.f32.f16.f16.f32 "
        "{%0,%1,%2,%3}, {%4,%5,%6,%7}, {%8,%9}, {%0,%1,%2,%3};"
        : "+f"(c[0]), "+f"(c[1]), "+f"(c[2]), "+f"(c[3])
        : "r"(a[0]), "r"(a[1]), "r"(a[2]), "r"(a[3]), "r"(b0), "r"(b1));
}
__device__ __forceinline__ void ldsm4(unsigned* r, unsigned addr) {
    asm volatile("ldmatrix.sync.aligned.m8n8.x4.shared.b16 {%0,%1,%2,%3}, [%4];"
        : "=r"(r[0]), "=r"(r[1]), "=r"(r[2]), "=r"(r[3]) : "r"(addr));
}
__device__ __forceinline__ void ldsm4t(unsigned* r, unsigned addr) {
    asm volatile("ldmatrix.sync.aligned.m8n8.x4.trans.shared.b16 {%0,%1,%2,%3}, [%4];"
        : "=r"(r[0]), "=r"(r[1]), "=r"(r[2]), "=r"(r[3]) : "r"(addr));
}
__device__ __forceinline__ void cp16(unsigned dst, const void* src) {
    asm volatile("cp.async.cg.shared.global [%0], [%1], 16;" :: "r"(dst), "l"(src));
}
__device__ __forceinline__ void cp_commit() {
    asm volatile("cp.async.commit_group;" ::: "memory");
}

// Rows are 64 halves = 128 bytes = 8 chunks of 16B; XOR swizzle on chunks.
__device__ __forceinline__ unsigned hswz(int row, int chunk) {   // byte offset
    return (unsigned)(row * 128 + (((chunk ^ (row & 7)) << 4)));
}

// ---------------------------------------------------------------------------
// fp32 -> fp16 pre-conversion (x, qkv_w, proj_w) — single fused launch
// ---------------------------------------------------------------------------
#define NX (M_*C_)
#define NQW (3*C_*C_)
#define NPW (C_*C_)

__global__ __launch_bounds__(256) void cvt_kernel(const float* __restrict__ x,
                                                  const float* __restrict__ qw,
                                                  const float* __restrict__ pw)
{
    int i = (blockIdx.x * 256 + threadIdx.x) * 8;
    const float* src;
    __half* dst;
    if (i < NX)            { src = x + i;              dst = xh_g + i; }
    else if (i < NX + NQW) { src = qw + (i - NX);      dst = qwh_g + (i - NX); }
    else                   { src = pw + (i - NX - NQW); dst = pwh_g + (i - NX - NQW); }
    float4 a = *(const float4*)src;
    float4 b = *(const float4*)(src + 4);
    *(uint4*)dst = cvt8(a, b);
}

// ---------------------------------------------------------------------------
// GEMM core: C_tile[128x128] = A[128xK] * W[128xK]^T, K=1024, fp16 in gmem.
// 128 threads, 4 warps (2x2), warp tile 64x64. Stage = 64 K-halves (128B rows),
// cp.async 3-stage ring, 1 barrier per stage.  (R14, passing)
// ---------------------------------------------------------------------------
#define STGB 32768   // bytes per stage (A 16KB + B 16KB)
#define NSTG 16      // 1024 / 64
#define GEMM_SMEM (3*STGB)

__device__ __forceinline__ void g_issue(unsigned sb, unsigned ring,
                                        const __half* Ap, const __half* Wp,
                                        int kc, int lrow, int lch)
{
    #pragma unroll
    for (int t = 0; t < 8; t++)
        cp16(sb + ring + hswz(lrow + 16 * t, lch), Ap + (size_t)(16 * t) * C_ + kc);
    #pragma unroll
    for (int t = 0; t < 8; t++)
        cp16(sb + ring + 16384u + hswz(lrow + 16 * t, lch), Wp + (size_t)(16 * t) * C_ + kc);
}

#define KSTEPH(ks)                                                          \
    {                                                                       \
        unsigned af[4][4], bf[4][4];                                        \
        _Pragma("unroll")                                                   \
        for (int i = 0; i < 4; i++)                                         \
            ldsm4(af[i], abase + hswz(wm * 64 + i * 16 + mrow_l, 2 * (ks) + chk_l)); \
        _Pragma("unroll")                                                   \
        for (int j = 0; j < 4; j++)                                         \
            ldsm4(bf[j], bbase + hswz(wn * 64 + j * 16 + mrow_l, 2 * (ks) + chk_l)); \
        _Pragma("unroll")                                                   \
        for (int i = 0; i < 4; i++)                                         \
            _Pragma("unroll")                                               \
            for (int j = 0; j < 4; j++) {                                   \
                mma16(acc[i][2 * j],     af[i], bf[j][0], bf[j][2]);        \
                mma16(acc[i][2 * j + 1], af[i], bf[j][1], bf[j][3]);        \
            }                                                               \
    }

__device__ __forceinline__ void gemm_h(const __half* __restrict__ A,
                                       const __half* __restrict__ W,
                                       int bm, int bn,
                                       float acc[4][8][4], char* smb)
{
    int tid = threadIdx.x, wid = tid >> 5, lane = tid & 31;
    int wm = wid >> 1, wn = wid & 1;
    unsigned sb = (unsigned)__cvta_generic_to_shared(smb);

    int lrow = tid >> 3;            // 0..15, rows +16t
    int lch = tid & 7;              // 16B chunk
    int mrow_l = (lane & 7) + (((lane >> 3) & 1) << 3);
    int chk_l = lane >> 4;

    const __half* Ap = A + (size_t)(bm + lrow) * C_ + lch * 8;
    const __half* Wp = W + (size_t)(bn + lrow) * C_ + lch * 8;

    g_issue(sb, 0, Ap, Wp, 0, lrow, lch);  cp_commit();
    g_issue(sb, STGB, Ap, Wp, 64, lrow, lch);  cp_commit();

    for (int s = 0; s < NSTG; s++) {
        if (s < NSTG - 1) asm volatile("cp.async.wait_group 1;" ::: "memory");
        else              asm volatile("cp.async.wait_group 0;" ::: "memory");
        __syncthreads();
        if (s + 2 < NSTG) {
            g_issue(sb, (unsigned)((s + 2) % 3) * STGB, Ap, Wp, (s + 2) * 64, lrow, lch);
            cp_commit();
        }
        unsigned abase = sb + (unsigned)(s % 3) * STGB;
        unsigned bbase = abase + 16384u;
        KSTEPH(0)
        KSTEPH(1)
        KSTEPH(2)
        KSTEPH(3)
    }
    __syncthreads();
}

// ---------------------------------------------------------------------------
// GEMM 1: qkv = x @ qkv_w^T -> fp16 q(scaled)/k/v [B,H,N,D]
// ---------------------------------------------------------------------------
#define SC2F 0.18033688f   // 0.125 * log2(e)

__global__ __launch_bounds__(128, 2) void qkv_gemm()
{
    extern __shared__ char smc[];
    int bm = blockIdx.y * 128, bn = blockIdx.x * 128;
    float acc[4][8][4];
    #pragma unroll
    for (int i = 0; i < 4; i++)
        #pragma unroll
        for (int j = 0; j < 8; j++)
            #pragma unroll
            for (int q = 0; q < 4; q++) acc[i][j][q] = 0.f;

    gemm_h(xh_g, qwh_g, bm, bn, acc, smc);

    int tid = threadIdx.x, wid = tid >> 5, lane = tid & 31;
    int wm = wid >> 1, wn = wid & 1;
    int g = lane >> 2, tg = lane & 3;

    #pragma unroll
    for (int i = 0; i < 4; i++) {
        #pragma unroll
        for (int j = 0; j < 8; j++) {
            int col = bn + wn * 64 + j * 8 + 2 * tg;
            int three = col >> 10, rem = col & 1023;
            int h = rem >> 6, d = rem & 63;
            __half* dst = (three == 0) ? qh_g : (three == 1 ? kh_g : vh_g);
            float sc = (three == 0) ? SC2F : 1.0f;
            #pragma unroll
            for (int half = 0; half < 2; half++) {
                int row = bm + wm * 64 + i * 16 + g + half * 8;
                int b = row >> 11, n = row & (N_ - 1);
                *(unsigned*)(dst + (((size_t)b * H_ + h) * N_ + n) * D_ + d) =
                    h2(acc[i][j][half * 2] * sc, acc[i][j][half * 2 + 1] * sc);
            }
        }
    }
}

// ---------------------------------------------------------------------------
// GEMM 2: out = atth @ proj_w^T + proj_b  (fp32 out)
// ---------------------------------------------------------------------------
__global__ __launch_bounds__(128, 2) void proj_gemm(const float* __restrict__ bias,
                                                    float* __restrict__ out)
{
    extern __shared__ char smc[];
    int bm = blockIdx.y * 128, bn = blockIdx.x * 128;
    float acc[4][8][4];
    #pragma unroll
    for (int i = 0; i < 4; i++)
        #pragma unroll
        for (int j = 0; j < 8; j++)
            #pragma unroll
            for (int q = 0; q < 4; q++) acc[i][j][q] = 0.f;

    gemm_h(atth_g, pwh_g, bm, bn, acc, smc);

    int tid = threadIdx.x, wid = tid >> 5, lane = tid & 31;
    int wm = wid >> 1, wn = wid & 1;
    int g = lane >> 2, tg = lane & 3;

    #pragma unroll
    for (int i = 0; i < 4; i++) {
        #pragma unroll
        for (int j = 0; j < 8; j++) {
            int col = bn + wn * 64 + j * 8 + 2 * tg;
            float b0 = bias[col], b1 = bias[col + 1];
            #pragma unroll
            for (int half = 0; half < 2; half++) {
                int row = bm + wm * 64 + i * 16 + g + half * 8;
                float2 v = {acc[i][j][half * 2] + b0, acc[i][j][half * 2 + 1] + b1};
                *(float2*)(out + (size_t)row * C_ + col) = v;
            }
        }
    }
}

// ---------------------------------------------------------------------------
// Causal flash attention, fp16. Block = (qtile 128, head, batch), 4 warps x
// 32 q-rows. cp.async Q + double-buffered K/V; V via ldmatrix.trans.
// P kept IN REGISTERS (S C-fragment == PV A-fragment after h2 packing).
// smem: Q [0,16K) | slot0 [16K,32K) | slot1 [32K,48K)  = 48KB.
// ---------------------------------------------------------------------------
#define QSB 0
#define RK(r) (16384u + (unsigned)(r) * 16384u)
#define RV(r) (RK(r) + 8192u)
#define ATT_SMEM 49152

__device__ __forceinline__ void kv_issue(unsigned sb, int ring, int kt,
                                         const __half* Kg, const __half* Vg,
                                         int krow, int kch)
{
    #pragma unroll
    for (int t = 0; t < 2; t++) {
        int row = krow + 32 * t;
        #pragma unroll
        for (int cc = 0; cc < 2; cc++) {
            int ch = kch + 4 * cc;
            const __half* ks = Kg + (size_t)(kt * 64 + row) * D_ + ch * 8;
            const __half* vs = Vg + (size_t)(kt * 64 + row) * D_ + ch * 8;
            cp16(sb + RK(ring) + hswz(row, ch), ks);
            cp16(sb + RV(ring) + hswz(row, ch), vs);
        }
    }
}

__global__ __launch_bounds__(128, 2) void attn_kernel()
{
    extern __shared__ char smc[];
    unsigned sb = (unsigned)__cvta_generic_to_shared(smc);

    int qt = (int)(gridDim.x - 1 - blockIdx.x);   // heavy tiles first
    int hh = blockIdx.y, b = blockIdx.z;
    int tid = threadIdx.x, w = tid >> 5, lane = tid & 31;
    int g = lane >> 2, tg = lane & 3;
    int wr = w * 32;

    int mrow_l = (lane & 7) + (((lane >> 3) & 1) << 3);
    int chk_l = lane >> 4;

    const __half* Qg = qh_g + ((size_t)b * H_ + hh) * N_ * D_;
    const __half* Kg = kh_g + ((size_t)b * H_ + hh) * N_ * D_;
    const __half* Vg = vh_g + ((size_t)b * H_ + hh) * N_ * D_;

    int lrow = tid >> 3, lch = tid & 7;            // Q loader
    int krow = tid >> 2, kch = tid & 3;            // K/V loader

    // prologue: Q tile + KV tile 0 in one group
    #pragma unroll
    for (int t = 0; t < 8; t++)
        cp16(sb + QSB + hswz(lrow + 16 * t, lch),
             Qg + (size_t)(qt * 128 + lrow + 16 * t) * D_ + lch * 8);
    kv_issue(sb, 0, 0, Kg, Vg, krow, kch);
    cp_commit();

    float o[2][8][4];
    #pragma unroll
    for (int i = 0; i < 2; i++)
        #pragma unroll
        for (int nt = 0; nt < 8; nt++)
            #pragma unroll
            for (int q = 0; q < 4; q++) o[i][nt][q] = 0.f;
    float mrow[2][2], lrow_[2][2];
    #pragma unroll
    for (int i = 0; i < 2; i++) { mrow[i][0] = mrow[i][1] = -1e30f; lrow_[i][0] = lrow_[i][1] = 0.f; }

    int nkt = 2 * qt + 2;
    for (int kt = 0; kt < nkt; kt++) {
        __syncthreads();                 // prior tile's ring reads complete
        if (kt + 1 < nkt) {
            kv_issue(sb, (kt + 1) & 1, kt + 1, Kg, Vg, krow, kch);
            cp_commit();
            asm volatile("cp.async.wait_group 1;" ::: "memory");
        } else {
            asm volatile("cp.async.wait_group 0;" ::: "memory");
        }
        __syncthreads();                 // stage kt visible

        bool active = !(kt * 64 > qt * 128 + wr + 31);
        unsigned kbase = sb + RK(kt & 1);
        unsigned vbase = sb + RV(kt & 1);

        if (active) {
            // S = Q K^T  (k16 steps)
            float s[2][8][4];
            #pragma unroll
            for (int i = 0; i < 2; i++)
                #pragma unroll
                for (int nt = 0; nt < 8; nt++)
                    #pragma unroll
                    for (int q = 0; q < 4; q++) s[i][nt][q] = 0.f;

            #pragma unroll
            for (int ks = 0; ks < 4; ks++) {
                unsigned kf[4][4];
                #pragma unroll
                for (int jp = 0; jp < 4; jp++)
                    ldsm4(kf[jp], kbase + hswz(jp * 16 + mrow_l, 2 * ks + chk_l));
                #pragma unroll
                for (int i = 0; i < 2; i++) {
                    unsigned qf[4];
                    ldsm4(qf, sb + QSB + hswz(wr + i * 16 + mrow_l, 2 * ks + chk_l));
                    #pragma unroll
                    for (int jp = 0; jp < 4; jp++) {
                        mma16(s[i][2 * jp],     qf, kf[jp][0], kf[jp][2]);
                        mma16(s[i][2 * jp + 1], qf, kf[jp][1], kf[jp][3]);
                    }
                }
            }

            // causal mask (tiles straddling the diagonal)
            if (kt * 64 + 63 > qt * 128 + wr) {
                #pragma unroll
                for (int i = 0; i < 2; i++) {
                    int row0 = qt * 128 + wr + i * 16 + g;
                    #pragma unroll
                    for (int nt = 0; nt < 8; nt++) {
                        int c0 = kt * 64 + nt * 8 + 2 * tg;
                        if (c0 > row0)         s[i][nt][0] = -1e30f;
                        if (c0 + 1 > row0)     s[i][nt][1] = -1e30f;
                        if (c0 > row0 + 8)     s[i][nt][2] = -1e30f;
                        if (c0 + 1 > row0 + 8) s[i][nt][3] = -1e30f;
                    }
                }
            }

            // online softmax (exp2 domain) — exp values kept in s[][][]
            #pragma unroll
            for (int i = 0; i < 2; i++) {
                float mx0 = -1e30f, mx1 = -1e30f;
                #pragma unroll
                for (int nt = 0; nt < 8; nt++) {
                    mx0 = fmaxf(mx0, fmaxf(s[i][nt][0], s[i][nt][1]));
                    mx1 = fmaxf(mx1, fmaxf(s[i][nt][2], s[i][nt][3]));
                }
                mx0 = fmaxf(mx0, __shfl_xor_sync(0xffffffffu, mx0, 1));
                mx0 = fmaxf(mx0, __shfl_xor_sync(0xffffffffu, mx0, 2));
                mx1 = fmaxf(mx1, __shfl_xor_sync(0xffffffffu, mx1, 1));
                mx1 = fmaxf(mx1, __shfl_xor_sync(0xffffffffu, mx1, 2));

                float nm0 = fmaxf(mrow[i][0], mx0), nm1 = fmaxf(mrow[i][1], mx1);
                float a0 = ex2(mrow[i][0] - nm0), a1 = ex2(mrow[i][1] - nm1);
                mrow[i][0] = nm0; mrow[i][1] = nm1;

                float ls0 = 0.f, ls1 = 0.f;
                #pragma unroll
                for (int nt = 0; nt < 8; nt++) {
                    s[i][nt][0] = ex2(s[i][nt][0] - nm0);
                    s[i][nt][1] = ex2(s[i][nt][1] - nm0);
                    s[i][nt][2] = ex2(s[i][nt][2] - nm1);
                    s[i][nt][3] = ex2(s[i][nt][3] - nm1);
                    ls0 += s[i][nt][0] + s[i][nt][1];
                    ls1 += s[i][nt][2] + s[i][nt][3];
                }
                ls0 += __shfl_xor_sync(0xffffffffu, ls0, 1);
                ls0 += __shfl_xor_sync(0xffffffffu, ls0, 2);
                ls1 += __shfl_xor_sync(0xffffffffu, ls1, 1);
                ls1 += __shfl_xor_sync(0xffffffffu, ls1, 2);
                lrow_[i][0] = lrow_[i][0] * a0 + ls0;
                lrow_[i][1] = lrow_[i][1] * a1 + ls1;

                #pragma unroll
                for (int nt = 0; nt < 8; nt++) {
                    o[i][nt][0] *= a0; o[i][nt][1] *= a0;
                    o[i][nt][2] *= a1; o[i][nt][3] *= a1;
                }
            }

            // O += P V  (P packed from registers: S C-frag == PV A-frag;
            //            V via ldmatrix.trans on [key][d])
            #pragma unroll
            for (int ks = 0; ks < 4; ks++) {
                unsigned vf[4][4];
                #pragma unroll
                for (int nt2 = 0; nt2 < 4; nt2++)
                    ldsm4t(vf[nt2], vbase + hswz(16 * ks + mrow_l, 2 * nt2 + chk_l));
                #pragma unroll
                for (int i = 0; i < 2; i++) {
                    unsigned pf[4];
                    pf[0] = h2(s[i][2 * ks][0],     s[i][2 * ks][1]);
                    pf[1] = h2(s[i][2 * ks][2],     s[i][2 * ks][3]);
                    pf[2] = h2(s[i][2 * ks + 1][0], s[i][2 * ks + 1][1]);
                    pf[3] = h2(s[i][2 * ks + 1][2], s[i][2 * ks + 1][3]);
                    #pragma unroll
                    for (int nt2 = 0; nt2 < 4; nt2++) {
                        mma16(o[i][2 * nt2],     pf, vf[nt2][0], vf[nt2][1]);
                        mma16(o[i][2 * nt2 + 1], pf, vf[nt2][2], vf[nt2][3]);
                    }
                }
            }
        }
    }

    // epilogue: normalize + write fp16 [B,N,C]
    __half* Og = atth_g + (size_t)b * N_ * C_ + (size_t)hh * 64;
    #pragma unroll
    for (int i = 0; i < 2; i++) {
        #pragma unroll
        for (int half = 0; half < 2; half++) {
            float inv = 1.f / lrow_[i][half];
            int row = qt * 128 + wr + i * 16 + g + half * 8;
            #pragma unroll
            for (int nt = 0; nt < 8; nt++) {
                int d = nt * 8 + 2 * tg;
                *(unsigned*)(Og + (size_t)row * C_ + d) =
                    h2(o[i][nt][half * 2] * inv, o[i][nt][half * 2 + 1] * inv);
            }
        }
    }
}

// ---------------------------------------------------------------------------
extern "C" void kernel_launch(void* const* d_in, const int* in_sizes, int n_in,
                              void* d_out, int out_size)
{
    const float* x      = (const float*)d_in[0];
    const float* qkv_w  = (const float*)d_in[1];
    const float* proj_w = (const float*)d_in[2];
    const float* proj_b = (const float*)d_in[3];
    float* out = (float*)d_out;

    cudaFuncSetAttribute(qkv_gemm, cudaFuncAttributeMaxDynamicSharedMemorySize, GEMM_SMEM);
    cudaFuncSetAttribute(proj_gemm, cudaFuncAttributeMaxDynamicSharedMemorySize, GEMM_SMEM);
    cudaFuncSetAttribute(attn_kernel, cudaFuncAttributeMaxDynamicSharedMemorySize, ATT_SMEM);

    cvt_kernel<<<(NX + NQW + NPW) / (256 * 8), 256>>>(x, qkv_w, proj_w);
    qkv_gemm<<<dim3(24, 64), 128, GEMM_SMEM>>>();
    attn_kernel<<<dim3(N_ / 128, H_, B_), 128, ATT_SMEM>>>();
    proj_gemm<<<dim3(8, 64), 128, GEMM_SMEM>>>(proj_b, out);
}